// round 3
// baseline (speedup 1.0000x reference)
#include <cuda_runtime.h>
#include <cuda_bf16.h>
#include <cstdint>

#define NN 100000
#define NE 3200000
#define NG 256

// ---------------- scratch (device globals; no allocation allowed) -------------
__device__ int   g_cnt[NN];
__device__ int   g_rowptr[NN + 1];
__device__ int   g_cursor[NN];
__device__ int   g_col[NE];
__device__ float g_wgt[NE];
__device__ float g_is[NN];                 // inv sqrt degree
__device__ float g_bufA[(size_t)NN * 512];
__device__ float g_bufB[(size_t)NN * 512];
__device__ float g_bufC[(size_t)NN * 1024];
__device__ float g_gsum[NG * 4];
__device__ int   g_gcnt[NG];

// ---------------- small utility kernels ----------------
__global__ void zero_kernel() {
    int i = blockIdx.x * blockDim.x + threadIdx.x;
    if (i < NN) g_cnt[i] = 0;
    if (i < NG * 4) g_gsum[i] = 0.f;
    if (i < NG) g_gcnt[i] = 0;
}

__global__ void hist_kernel(const int* __restrict__ dst) {
    int e = blockIdx.x * blockDim.x + threadIdx.x;
    if (e < NE) atomicAdd(&g_cnt[dst[e]], 1);
}

__global__ void invsqrt_kernel() {
    int i = blockIdx.x * blockDim.x + threadIdx.x;
    if (i < NN) g_is[i] = rsqrtf((float)(g_cnt[i] + 1));   // +1 self loop
}

// single-block exclusive scan of g_cnt -> g_rowptr / g_cursor
__global__ void scan_kernel() {
    __shared__ int sm[1024];
    const int tid = threadIdx.x;
    const int CH = (NN + 1023) / 1024;  // 98
    int base = tid * CH;
    int s = 0;
    for (int i = 0; i < CH; i++) {
        int idx = base + i;
        if (idx < NN) s += g_cnt[idx];
    }
    sm[tid] = s;
    __syncthreads();
    // Hillis-Steele inclusive scan
    for (int off = 1; off < 1024; off <<= 1) {
        int add = (tid >= off) ? sm[tid - off] : 0;
        __syncthreads();
        sm[tid] += add;
        __syncthreads();
    }
    int run = (tid == 0) ? 0 : sm[tid - 1];
    for (int i = 0; i < CH; i++) {
        int idx = base + i;
        if (idx < NN) {
            g_rowptr[idx] = run;
            g_cursor[idx] = run;
            run += g_cnt[idx];
        }
    }
    if (tid == 1023) g_rowptr[NN] = sm[1023];
}

__global__ void csr_fill_kernel(const int* __restrict__ src, const int* __restrict__ dst) {
    int e = blockIdx.x * blockDim.x + threadIdx.x;
    if (e >= NE) return;
    int d = dst[e];
    int s = src[e];
    int p = atomicAdd(&g_cursor[d], 1);
    g_col[p] = s;
    g_wgt[p] = g_is[s] * g_is[d];
}

// ---------------- aggregation: out[i] = sum_e w_e * h[src_e] + is^2 * h[i] ----
template <int H>
__global__ void agg_kernel(const float* __restrict__ h, float* __restrict__ out) {
    const int node = blockIdx.x * 4 + (threadIdx.x >> 5);
    if (node >= NN) return;
    const int lane = threadIdx.x & 31;
    constexpr int V = H / 128;  // float4 per lane

    float4 acc[V];
    float self = g_is[node];
    self = self * self;
    const float4* hrow = (const float4*)(h + (size_t)node * H);
#pragma unroll
    for (int v = 0; v < V; v++) {
        float4 t = hrow[lane + 32 * v];
        acc[v] = make_float4(t.x * self, t.y * self, t.z * self, t.w * self);
    }
    const int beg = g_rowptr[node];
    const int end = g_rowptr[node + 1];
    for (int p = beg; p < end; p++) {
        int s = g_col[p];
        float w = g_wgt[p];
        const float4* sr = (const float4*)(h + (size_t)s * H);
#pragma unroll
        for (int v = 0; v < V; v++) {
            float4 t = sr[lane + 32 * v];
            acc[v].x += w * t.x; acc[v].y += w * t.y;
            acc[v].z += w * t.z; acc[v].w += w * t.w;
        }
    }
    float4* orow = (float4*)(out + (size_t)node * H);
#pragma unroll
    for (int v = 0; v < V; v++) orow[lane + 32 * v] = acc[v];
}

// ---------------- fp32 tiled GEMM:  C[M,N] = act(A[M,K] @ W[K,N] + b) --------
// BM=BN=64, BK=16, 256 threads, 4x4 micro-tile per thread.
__global__ __launch_bounds__(256) void sgemm_kernel(
    const float* __restrict__ A, const float* __restrict__ W,
    const float* __restrict__ bias, float* __restrict__ C,
    int M, int K, int N, int relu) {
    __shared__ float As[16][68];   // [k][m], padded
    __shared__ float Bs[16][64];   // [k][n]

    const int tid = threadIdx.x;
    const int bm = blockIdx.y * 64;
    const int bn = blockIdx.x * 64;
    const int tx = tid & 15;       // n dir
    const int ty = tid >> 4;       // m dir

    const int a_r = tid >> 2;            // 0..63 row within tile
    const int a_c = (tid & 3) * 4;       // 0,4,8,12
    const int b_r = tid >> 4;            // 0..15
    const int b_c = (tid & 15) * 4;      // 0..60

    float acc[4][4] = {};

    for (int k0 = 0; k0 < K; k0 += 16) {
        float4 av = make_float4(0.f, 0.f, 0.f, 0.f);
        int gr = bm + a_r;
        if (gr < M) av = *(const float4*)(A + (size_t)gr * K + k0 + a_c);
        As[a_c + 0][a_r] = av.x;
        As[a_c + 1][a_r] = av.y;
        As[a_c + 2][a_r] = av.z;
        As[a_c + 3][a_r] = av.w;

        float4 bv = *(const float4*)(W + (size_t)(k0 + b_r) * N + bn + b_c);
        *(float4*)&Bs[b_r][b_c] = bv;
        __syncthreads();

#pragma unroll
        for (int k = 0; k < 16; k++) {
            float4 a4 = *(const float4*)&As[k][ty * 4];
            float4 b4 = *(const float4*)&Bs[k][tx * 4];
            float ar[4] = {a4.x, a4.y, a4.z, a4.w};
            float br[4] = {b4.x, b4.y, b4.z, b4.w};
#pragma unroll
            for (int i = 0; i < 4; i++)
#pragma unroll
                for (int j = 0; j < 4; j++) acc[i][j] += ar[i] * br[j];
        }
        __syncthreads();
    }

#pragma unroll
    for (int i = 0; i < 4; i++) {
        int row = bm + ty * 4 + i;
        if (row >= M) continue;
#pragma unroll
        for (int j = 0; j < 4; j++) {
            int colg = bn + tx * 4 + j;
            float v = acc[i][j] + bias[colg];
            if (relu) v = fmaxf(v, 0.f);
            C[(size_t)row * N + colg] = v;
        }
    }
}

// ---------------- final layer (512 -> 4) fused with graph pooling ------------
__global__ void final_kernel(const float* __restrict__ m2, const float* __restrict__ lw3,
                             const float* __restrict__ lb3, const int* __restrict__ batch) {
    const int node = blockIdx.x * 4 + (threadIdx.x >> 5);
    if (node >= NN) return;
    const int lane = threadIdx.x & 31;
    float a0 = 0.f, a1 = 0.f, a2 = 0.f, a3 = 0.f;
    const float* row = m2 + (size_t)node * 512;
    for (int k = lane; k < 512; k += 32) {
        float v = row[k];
        float4 w = *(const float4*)(lw3 + k * 4);
        a0 += v * w.x; a1 += v * w.y; a2 += v * w.z; a3 += v * w.w;
    }
#pragma unroll
    for (int off = 16; off > 0; off >>= 1) {
        a0 += __shfl_down_sync(0xffffffffu, a0, off);
        a1 += __shfl_down_sync(0xffffffffu, a1, off);
        a2 += __shfl_down_sync(0xffffffffu, a2, off);
        a3 += __shfl_down_sync(0xffffffffu, a3, off);
    }
    if (lane == 0) {
        int g = batch[node];
        atomicAdd(&g_gsum[g * 4 + 0], a0 + lb3[0]);
        atomicAdd(&g_gsum[g * 4 + 1], a1 + lb3[1]);
        atomicAdd(&g_gsum[g * 4 + 2], a2 + lb3[2]);
        atomicAdd(&g_gsum[g * 4 + 3], a3 + lb3[3]);
        atomicAdd(&g_gcnt[g], 1);
    }
}

__global__ void finalize_kernel(float* __restrict__ out) {
    int i = blockIdx.x * blockDim.x + threadIdx.x;
    if (i < NG * 4) {
        float c = fmaxf((float)g_gcnt[i >> 2], 1.f);
        out[i] = g_gsum[i] / c;
    }
}

// ---------------- launch ----------------
extern "C" void kernel_launch(void* const* d_in, const int* in_sizes, int n_in,
                              void* d_out, int out_size) {
    const float* x    = (const float*)d_in[0];
    const int*   ei   = (const int*)d_in[1];     // [2, NE]
    const int*   bat  = (const int*)d_in[2];
    const float* W1   = (const float*)d_in[3];
    const float* b1   = (const float*)d_in[4];
    const float* W2   = (const float*)d_in[5];
    const float* b2   = (const float*)d_in[6];
    const float* W3   = (const float*)d_in[7];
    const float* b3   = (const float*)d_in[8];
    const float* lw1  = (const float*)d_in[9];
    const float* lb1  = (const float*)d_in[10];
    const float* lw2  = (const float*)d_in[11];
    const float* lb2  = (const float*)d_in[12];
    const float* lw3  = (const float*)d_in[13];
    const float* lb3  = (const float*)d_in[14];
    float* out = (float*)d_out;

    const int* src = ei;
    const int* dst = ei + NE;

    float *bufA, *bufB, *bufC;
    cudaGetSymbolAddress((void**)&bufA, g_bufA);
    cudaGetSymbolAddress((void**)&bufB, g_bufB);
    cudaGetSymbolAddress((void**)&bufC, g_bufC);

    // ---- graph preprocessing ----
    zero_kernel<<<(NN + 255) / 256, 256>>>();
    hist_kernel<<<(NE + 255) / 256, 256>>>(dst);
    invsqrt_kernel<<<(NN + 255) / 256, 256>>>();
    scan_kernel<<<1, 1024>>>();
    csr_fill_kernel<<<(NE + 255) / 256, 256>>>(src, dst);

    const int aggBlocks = (NN + 3) / 4;

    // ---- layer 1: agg(x) @ W1 + b1, relu ----
    agg_kernel<128><<<aggBlocks, 128>>>(x, bufA);
    sgemm_kernel<<<dim3(128 / 64, (NN + 63) / 64), 256>>>(bufA, W1, b1, bufB, NN, 128, 128, 1);

    // ---- layer 2: agg(h1) @ W2 + b2, relu ----
    agg_kernel<128><<<aggBlocks, 128>>>(bufB, bufA);
    sgemm_kernel<<<dim3(256 / 64, (NN + 63) / 64), 256>>>(bufA, W2, b2, bufB, NN, 128, 256, 1);

    // ---- layer 3: agg(h2) @ W3 + b3 (no relu) ----
    agg_kernel<256><<<aggBlocks, 128>>>(bufB, bufA);
    sgemm_kernel<<<dim3(512 / 64, (NN + 63) / 64), 256>>>(bufA, W3, b3, bufB, NN, 256, 512, 0);

    // ---- MLP head ----
    sgemm_kernel<<<dim3(1024 / 64, (NN + 63) / 64), 256>>>(bufB, lw1, lb1, bufC, NN, 512, 1024, 1);
    sgemm_kernel<<<dim3(512 / 64, (NN + 63) / 64), 256>>>(bufC, lw2, lb2, bufA, NN, 1024, 512, 1);

    // ---- final layer + pooling ----
    final_kernel<<<aggBlocks, 128>>>(bufA, lw3, lb3, bat);
    finalize_kernel<<<(NG * 4 + 255) / 256, 256>>>(out);
}

// round 6
// speedup vs baseline: 2.1233x; 2.1233x over previous
#include <cuda_runtime.h>
#include <cuda_bf16.h>
#include <cstdint>

#define NN 100000
#define NE 3200000
#define NG 256

// ================= device scratch (no allocations allowed) =================
__device__ int   g_cnt[NN];
__device__ int   g_rowptr[NN + 1];
__device__ int   g_cursor[NN];
__device__ int   g_col[NE];
__device__ float g_wgt[NE];
__device__ float g_is[NN];
__device__ float g_bufA[(size_t)NN * 512];
__device__ float g_bufB[(size_t)NN * 512];
__device__ __nv_bfloat16 g_A2[(size_t)NN * 3072];   // split activations [hi|lo|hi]
__device__ __nv_bfloat16 g_B2[(size_t)NN * 3072];
__device__ __nv_bfloat16 g_W2[2 << 20];             // split weights [hi|hi|lo], N-major
__device__ float g_gsum[NG * 4];
__device__ int   g_gcnt[NG];

__device__ __forceinline__ uint32_t smem_u32(const void* p) {
    uint32_t a;
    asm("{ .reg .u64 t; cvta.to.shared.u64 t, %1; cvt.u32.u64 %0, t; }" : "=r"(a) : "l"(p));
    return a;
}

// ================= graph preprocessing kernels =================
__global__ void zero_kernel() {
    int i = blockIdx.x * blockDim.x + threadIdx.x;
    if (i < NN) g_cnt[i] = 0;
    if (i < NG * 4) g_gsum[i] = 0.f;
    if (i < NG) g_gcnt[i] = 0;
}

__global__ void hist_kernel(const int* __restrict__ dst) {
    int e = blockIdx.x * blockDim.x + threadIdx.x;
    if (e < NE) atomicAdd(&g_cnt[dst[e]], 1);
}

__global__ void invsqrt_kernel() {
    int i = blockIdx.x * blockDim.x + threadIdx.x;
    if (i < NN) g_is[i] = rsqrtf((float)(g_cnt[i] + 1));
}

__global__ void scan_kernel() {
    __shared__ int sm[1024];
    const int tid = threadIdx.x;
    const int CH = (NN + 1023) / 1024;
    int base = tid * CH;
    int s = 0;
    for (int i = 0; i < CH; i++) {
        int idx = base + i;
        if (idx < NN) s += g_cnt[idx];
    }
    sm[tid] = s;
    __syncthreads();
    for (int off = 1; off < 1024; off <<= 1) {
        int add = (tid >= off) ? sm[tid - off] : 0;
        __syncthreads();
        sm[tid] += add;
        __syncthreads();
    }
    int run = (tid == 0) ? 0 : sm[tid - 1];
    for (int i = 0; i < CH; i++) {
        int idx = base + i;
        if (idx < NN) {
            g_rowptr[idx] = run;
            g_cursor[idx] = run;
            run += g_cnt[idx];
        }
    }
    if (tid == 1023) g_rowptr[NN] = sm[1023];
}

__global__ void csr_fill_kernel(const int* __restrict__ src, const int* __restrict__ dst) {
    int e = blockIdx.x * blockDim.x + threadIdx.x;
    if (e >= NE) return;
    int d = dst[e];
    int s = src[e];
    int p = atomicAdd(&g_cursor[d], 1);
    g_col[p] = s;
    g_wgt[p] = g_is[s] * g_is[d];
}

// ================= aggregation =================
template <int H>
__global__ void agg_kernel(const float* __restrict__ h, float* __restrict__ out) {
    const int node = blockIdx.x * 4 + (threadIdx.x >> 5);
    if (node >= NN) return;
    const int lane = threadIdx.x & 31;
    constexpr int V = H / 128;

    float4 acc[V];
    float self = g_is[node];
    self = self * self;
    const float4* hrow = (const float4*)(h + (size_t)node * H);
#pragma unroll
    for (int v = 0; v < V; v++) {
        float4 t = hrow[lane + 32 * v];
        acc[v] = make_float4(t.x * self, t.y * self, t.z * self, t.w * self);
    }
    const int beg = g_rowptr[node];
    const int end = g_rowptr[node + 1];
    for (int p = beg; p < end; p++) {
        int s = g_col[p];
        float w = g_wgt[p];
        const float4* sr = (const float4*)(h + (size_t)s * H);
#pragma unroll
        for (int v = 0; v < V; v++) {
            float4 t = sr[lane + 32 * v];
            acc[v].x += w * t.x; acc[v].y += w * t.y;
            acc[v].z += w * t.z; acc[v].w += w * t.w;
        }
    }
    float4* orow = (float4*)(out + (size_t)node * H);
#pragma unroll
    for (int v = 0; v < V; v++) orow[lane + 32 * v] = acc[v];
}

// ================= SIMT GEMM for small conv layers (L1, L2) =================
__global__ __launch_bounds__(256) void sgemm_kernel(
    const float* __restrict__ A, const float* __restrict__ W,
    const float* __restrict__ bias, float* __restrict__ C,
    int M, int K, int N, int relu) {
    __shared__ float As[16][68];
    __shared__ float Bs[16][64];

    const int tid = threadIdx.x;
    const int bm = blockIdx.y * 64;
    const int bn = blockIdx.x * 64;
    const int tx = tid & 15;
    const int ty = tid >> 4;

    const int a_r = tid >> 2;
    const int a_c = (tid & 3) * 4;
    const int b_r = tid >> 4;
    const int b_c = (tid & 15) * 4;

    float acc[4][4] = {};

    for (int k0 = 0; k0 < K; k0 += 16) {
        float4 av = make_float4(0.f, 0.f, 0.f, 0.f);
        int gr = bm + a_r;
        if (gr < M) av = *(const float4*)(A + (size_t)gr * K + k0 + a_c);
        As[a_c + 0][a_r] = av.x;
        As[a_c + 1][a_r] = av.y;
        As[a_c + 2][a_r] = av.z;
        As[a_c + 3][a_r] = av.w;

        float4 bv = *(const float4*)(W + (size_t)(k0 + b_r) * N + bn + b_c);
        *(float4*)&Bs[b_r][b_c] = bv;
        __syncthreads();

#pragma unroll
        for (int k = 0; k < 16; k++) {
            float4 a4 = *(const float4*)&As[k][ty * 4];
            float4 b4 = *(const float4*)&Bs[k][tx * 4];
            float ar[4] = {a4.x, a4.y, a4.z, a4.w};
            float br[4] = {b4.x, b4.y, b4.z, b4.w};
#pragma unroll
            for (int i = 0; i < 4; i++)
#pragma unroll
                for (int j = 0; j < 4; j++) acc[i][j] += ar[i] * br[j];
        }
        __syncthreads();
    }

#pragma unroll
    for (int i = 0; i < 4; i++) {
        int row = bm + ty * 4 + i;
        if (row >= M) continue;
#pragma unroll
        for (int j = 0; j < 4; j++) {
            int colg = bn + tx * 4 + j;
            float v = acc[i][j] + bias[colg];
            if (relu) v = fmaxf(v, 0.f);
            C[(size_t)row * N + colg] = v;
        }
    }
}

// ================= fp32 -> split-bf16 conversion =================
// W[K][N] fp32 -> g_W2 rows n of length 3K: [Whi | Whi | Wlo]
__global__ void wconv_kernel(const float* __restrict__ W, int K, int N) {
    int idx = blockIdx.x * blockDim.x + threadIdx.x;
    if (idx >= N * K) return;
    int n = idx / K, k = idx - n * K;
    float v = W[(size_t)k * N + n];
    __nv_bfloat16 hi = __float2bfloat16(v);
    __nv_bfloat16 lo = __float2bfloat16(v - __bfloat162float(hi));
    size_t base = (size_t)n * 3 * K;
    g_W2[base + k] = hi;
    g_W2[base + K + k] = hi;
    g_W2[base + 2 * K + k] = lo;
}

// A[M][K] fp32 -> out2 rows m of length 3K: [Ahi | Alo | Ahi]
__global__ void aconv_kernel(const float* __restrict__ A, __nv_bfloat16* __restrict__ out2,
                             int K, size_t total) {
    size_t i = blockIdx.x * (size_t)blockDim.x + threadIdx.x;
    if (i >= total) return;
    size_t m = i / (size_t)K;
    int k = (int)(i - m * K);
    float v = A[i];
    __nv_bfloat16 hi = __float2bfloat16(v);
    __nv_bfloat16 lo = __float2bfloat16(v - __bfloat162float(hi));
    __nv_bfloat16* row = out2 + m * (size_t)(3 * K);
    row[k] = hi;
    row[K + k] = lo;
    row[2 * K + k] = hi;
}

// ================= tensor-core GEMM via mma.sync (HMMA bf16) =================
// C[M,N] = act(A2[M,K3] @ W2[N,K3]^T + bias)
// CTA tile 128x128, BK=32, 8 warps (2M x 4N), warp tile 64x32, m16n8k16 atoms.
__device__ __forceinline__ void write_split(__nv_bfloat16* rowp, int N, int c,
                                            float v0, float v1) {
    __nv_bfloat16 h0 = __float2bfloat16(v0), h1 = __float2bfloat16(v1);
    __nv_bfloat16 l0 = __float2bfloat16(v0 - __bfloat162float(h0));
    __nv_bfloat16 l1 = __float2bfloat16(v1 - __bfloat162float(h1));
    uint32_t hp = (uint32_t)__bfloat16_as_ushort(h0) | ((uint32_t)__bfloat16_as_ushort(h1) << 16);
    uint32_t lp = (uint32_t)__bfloat16_as_ushort(l0) | ((uint32_t)__bfloat16_as_ushort(l1) << 16);
    *(uint32_t*)(rowp + c) = hp;
    *(uint32_t*)(rowp + N + c) = lp;
    *(uint32_t*)(rowp + 2 * N + c) = hp;
}

template <int OUTMODE>  // 0: fp32 out, 1: split-bf16 out (stride 3N)
__global__ __launch_bounds__(256) void gemm_mma(
    const __nv_bfloat16* __restrict__ A2, const __nv_bfloat16* __restrict__ W2,
    const float* __restrict__ bias, int M, int K3, int N, int relu,
    float* __restrict__ outF, __nv_bfloat16* __restrict__ out2) {
    __shared__ alignas(1024) char sA[2][8192];   // 128 rows x 64B (32 bf16), swizzled
    __shared__ alignas(1024) char sB[2][8192];

    const int tid = threadIdx.x;
    const int lane = tid & 31, wid = tid >> 5;
    const int wm = wid & 1, wn = wid >> 1;   // 2 (M) x 4 (N)
    const int m0 = blockIdx.y * 128, n0 = blockIdx.x * 128;
    const uint32_t aSm = smem_u32(sA), bSm = smem_u32(sB);
    const int nch = K3 >> 5;

    float acc[4][4][4];
#pragma unroll
    for (int i = 0; i < 4; i++)
#pragma unroll
        for (int j = 0; j < 4; j++)
#pragma unroll
            for (int q = 0; q < 4; q++) acc[i][j][q] = 0.f;

    auto fill = [&](int ci, int buf) {
        const int kb = ci * 64;  // byte offset along K3
#pragma unroll
        for (int i = 0; i < 2; i++) {
            int t2 = tid + i * 256;
            int r = t2 >> 2, c = t2 & 3;
            uint32_t soff = (uint32_t)(r * 64 + ((c ^ ((r >> 1) & 3)) * 16));
            {   // A (row may be out of range -> zero-fill)
                int row = m0 + r;
                int rowc = (row < M) ? row : (M - 1);
                const char* src = (const char*)(A2 + (size_t)rowc * K3) + kb + c * 16;
                uint32_t ssize = (row < M) ? 16u : 0u;
                uint32_t dst = aSm + buf * 8192 + soff;
                asm volatile("cp.async.cg.shared.global [%0], [%1], 16, %2;"
                             :: "r"(dst), "l"(src), "r"(ssize) : "memory");
            }
            {   // B (N multiple of 128 -> always in range)
                const char* src = (const char*)(W2 + (size_t)(n0 + r) * K3) + kb + c * 16;
                uint32_t dst = bSm + buf * 8192 + soff;
                asm volatile("cp.async.cg.shared.global [%0], [%1], 16;"
                             :: "r"(dst), "l"(src) : "memory");
            }
        }
        asm volatile("cp.async.commit_group;" ::: "memory");
    };

    auto compute = [&](int buf) {
        const uint32_t aB = aSm + buf * 8192, bB = bSm + buf * 8192;
#pragma unroll
        for (int ks = 0; ks < 2; ks++) {
            uint32_t af[4][4];
#pragma unroll
            for (int ma = 0; ma < 4; ma++) {
                int r = wm * 64 + ma * 16 + (lane & 15);
                int c = ks * 2 + (lane >> 4);
                uint32_t addr = aB + r * 64 + ((c ^ ((r >> 1) & 3)) * 16);
                asm volatile("ldmatrix.sync.aligned.m8n8.x4.shared.b16 {%0,%1,%2,%3}, [%4];"
                             : "=r"(af[ma][0]), "=r"(af[ma][1]), "=r"(af[ma][2]), "=r"(af[ma][3])
                             : "r"(addr));
            }
            uint32_t bf[4][2];
#pragma unroll
            for (int nb = 0; nb < 2; nb++) {
                int r = wn * 32 + nb * 16 + (lane & 7) + ((lane >> 4) & 1) * 8;
                int c = ks * 2 + ((lane >> 3) & 1);
                uint32_t addr = bB + r * 64 + ((c ^ ((r >> 1) & 3)) * 16);
                uint32_t r0, r1, r2, r3;
                asm volatile("ldmatrix.sync.aligned.m8n8.x4.shared.b16 {%0,%1,%2,%3}, [%4];"
                             : "=r"(r0), "=r"(r1), "=r"(r2), "=r"(r3) : "r"(addr));
                bf[nb * 2][0] = r0; bf[nb * 2][1] = r1;
                bf[nb * 2 + 1][0] = r2; bf[nb * 2 + 1][1] = r3;
            }
#pragma unroll
            for (int ma = 0; ma < 4; ma++)
#pragma unroll
                for (int na = 0; na < 4; na++)
                    asm volatile(
                        "mma.sync.aligned.m16n8k16.row.col.f32.bf16.bf16.f32 "
                        "{%0,%1,%2,%3}, {%4,%5,%6,%7}, {%8,%9}, {%0,%1,%2,%3};"
                        : "+f"(acc[ma][na][0]), "+f"(acc[ma][na][1]),
                          "+f"(acc[ma][na][2]), "+f"(acc[ma][na][3])
                        : "r"(af[ma][0]), "r"(af[ma][1]), "r"(af[ma][2]), "r"(af[ma][3]),
                          "r"(bf[na][0]), "r"(bf[na][1]));
        }
    };

    fill(0, 0);
    for (int ci = 0; ci < nch; ci++) {
        if (ci + 1 < nch) {
            fill(ci + 1, (ci + 1) & 1);
            asm volatile("cp.async.wait_group 1;" ::: "memory");
        } else {
            asm volatile("cp.async.wait_group 0;" ::: "memory");
        }
        __syncthreads();
        compute(ci & 1);
        __syncthreads();
    }

    // ---- epilogue ----
#pragma unroll
    for (int ma = 0; ma < 4; ma++) {
        int r0 = m0 + wm * 64 + ma * 16 + (lane >> 2);
#pragma unroll
        for (int na = 0; na < 4; na++) {
            int c = n0 + wn * 32 + na * 8 + (lane & 3) * 2;
            float b0v = __ldg(bias + c), b1v = __ldg(bias + c + 1);
            float v00 = acc[ma][na][0] + b0v, v01 = acc[ma][na][1] + b1v;
            float v10 = acc[ma][na][2] + b0v, v11 = acc[ma][na][3] + b1v;
            if (relu) {
                v00 = fmaxf(v00, 0.f); v01 = fmaxf(v01, 0.f);
                v10 = fmaxf(v10, 0.f); v11 = fmaxf(v11, 0.f);
            }
            if (OUTMODE == 0) {
                if (r0 < M) *(float2*)(outF + (size_t)r0 * N + c) = make_float2(v00, v01);
                if (r0 + 8 < M) *(float2*)(outF + (size_t)(r0 + 8) * N + c) = make_float2(v10, v11);
            } else {
                size_t st = (size_t)3 * N;
                if (r0 < M) write_split(out2 + (size_t)r0 * st, N, c, v00, v01);
                if (r0 + 8 < M) write_split(out2 + (size_t)(r0 + 8) * st, N, c, v10, v11);
            }
        }
    }
}

// ================= final layer + pooling =================
__global__ void final_kernel(const float* __restrict__ m2, const float* __restrict__ lw3,
                             const float* __restrict__ lb3, const int* __restrict__ batch) {
    const int node = blockIdx.x * 4 + (threadIdx.x >> 5);
    if (node >= NN) return;
    const int lane = threadIdx.x & 31;
    float a0 = 0.f, a1 = 0.f, a2 = 0.f, a3 = 0.f;
    const float* row = m2 + (size_t)node * 512;
    for (int k = lane; k < 512; k += 32) {
        float v = row[k];
        float4 w = *(const float4*)(lw3 + k * 4);
        a0 += v * w.x; a1 += v * w.y; a2 += v * w.z; a3 += v * w.w;
    }
#pragma unroll
    for (int off = 16; off > 0; off >>= 1) {
        a0 += __shfl_down_sync(0xffffffffu, a0, off);
        a1 += __shfl_down_sync(0xffffffffu, a1, off);
        a2 += __shfl_down_sync(0xffffffffu, a2, off);
        a3 += __shfl_down_sync(0xffffffffu, a3, off);
    }
    if (lane == 0) {
        int g = batch[node];
        atomicAdd(&g_gsum[g * 4 + 0], a0 + lb3[0]);
        atomicAdd(&g_gsum[g * 4 + 1], a1 + lb3[1]);
        atomicAdd(&g_gsum[g * 4 + 2], a2 + lb3[2]);
        atomicAdd(&g_gsum[g * 4 + 3], a3 + lb3[3]);
        atomicAdd(&g_gcnt[g], 1);
    }
}

__global__ void finalize_kernel(float* __restrict__ out) {
    int i = blockIdx.x * blockDim.x + threadIdx.x;
    if (i < NG * 4) {
        float c = fmaxf((float)g_gcnt[i >> 2], 1.f);
        out[i] = g_gsum[i] / c;
    }
}

// ================= launch =================
extern "C" void kernel_launch(void* const* d_in, const int* in_sizes, int n_in,
                              void* d_out, int out_size) {
    const float* x    = (const float*)d_in[0];
    const int*   ei   = (const int*)d_in[1];
    const int*   bat  = (const int*)d_in[2];
    const float* W1   = (const float*)d_in[3];
    const float* b1   = (const float*)d_in[4];
    const float* W2   = (const float*)d_in[5];
    const float* b2   = (const float*)d_in[6];
    const float* W3   = (const float*)d_in[7];
    const float* b3   = (const float*)d_in[8];
    const float* lw1  = (const float*)d_in[9];
    const float* lb1  = (const float*)d_in[10];
    const float* lw2  = (const float*)d_in[11];
    const float* lb2  = (const float*)d_in[12];
    const float* lw3  = (const float*)d_in[13];
    const float* lb3  = (const float*)d_in[14];
    float* out = (float*)d_out;

    const int* src = ei;
    const int* dst = ei + NE;

    float *bufA, *bufB;
    cudaGetSymbolAddress((void**)&bufA, g_bufA);
    cudaGetSymbolAddress((void**)&bufB, g_bufB);
    __nv_bfloat16 *A2, *B2, *W2s;
    cudaGetSymbolAddress((void**)&A2, g_A2);
    cudaGetSymbolAddress((void**)&B2, g_B2);
    cudaGetSymbolAddress((void**)&W2s, g_W2);   // FIX: proper device address (was host shadow)

    // ---- graph preprocessing ----
    zero_kernel<<<(NN + 255) / 256, 256>>>();
    hist_kernel<<<(NE + 255) / 256, 256>>>(dst);
    invsqrt_kernel<<<(NN + 255) / 256, 256>>>();
    scan_kernel<<<1, 1024>>>();
    csr_fill_kernel<<<(NE + 255) / 256, 256>>>(src, dst);

    const int aggBlocks = (NN + 3) / 4;
    const int tilesM = (NN + 127) / 128;   // 782

    // ---- layer 1 & 2 (small, SIMT fp32) ----
    agg_kernel<128><<<aggBlocks, 128>>>(x, bufA);
    sgemm_kernel<<<dim3(2, (NN + 63) / 64), 256>>>(bufA, W1, b1, bufB, NN, 128, 128, 1);

    agg_kernel<128><<<aggBlocks, 128>>>(bufB, bufA);
    sgemm_kernel<<<dim3(4, (NN + 63) / 64), 256>>>(bufA, W2, b2, bufB, NN, 128, 256, 1);

    // ---- layer 3 + MLP head on tensor cores (augmented-K bf16 split) ----
    agg_kernel<256><<<aggBlocks, 128>>>(bufB, bufA);
    aconv_kernel<<<(int)(((size_t)NN * 256 + 255) / 256), 256>>>(bufA, A2, 256, (size_t)NN * 256);

    // L3: [NN,768] @ [512,768]^T -> split out to B2 (stride 1536), no relu
    wconv_kernel<<<(512 * 256 + 255) / 256, 256>>>(W3, 256, 512);
    gemm_mma<1><<<dim3(4, tilesM), 256>>>(A2, W2s, b3, NN, 768, 512, 0, nullptr, B2);

    // MLP1: [NN,1536] @ [1024,1536]^T -> split out to A2 (stride 3072), relu
    wconv_kernel<<<(1024 * 512 + 255) / 256, 256>>>(lw1, 512, 1024);
    gemm_mma<1><<<dim3(8, tilesM), 256>>>(B2, W2s, lb1, NN, 1536, 1024, 1, nullptr, A2);

    // MLP2: [NN,3072] @ [512,3072]^T -> fp32 out to bufA, relu
    wconv_kernel<<<(512 * 1024 + 255) / 256, 256>>>(lw2, 1024, 512);
    gemm_mma<0><<<dim3(4, tilesM), 256>>>(A2, W2s, lb2, NN, 3072, 512, 1, bufA, nullptr);

    // ---- final layer + pooling ----
    final_kernel<<<aggBlocks, 128>>>(bufA, lw3, lb3, bat);
    finalize_kernel<<<(NG * 4 + 255) / 256, 256>>>(out);
}

// round 7
// speedup vs baseline: 2.5537x; 1.2027x over previous
#include <cuda_runtime.h>
#include <cuda_bf16.h>
#include <cstdint>

#define NN 100000
#define NE 3200000
#define NG 256
#define NBLK 391   // ceil(NN/256)

// ================= device scratch (no allocations allowed) =================
__device__ int   g_cnt[NN];
__device__ int   g_rowptr[NN + 1];
__device__ int   g_cursor[NN];
__device__ int   g_bsum[NBLK];
__device__ int   g_col[NE];
__device__ float g_wgt[NE];
__device__ float g_is[NN];
__device__ float g_bufA[(size_t)NN * 512];
__device__ float g_bufB[(size_t)NN * 512];
__device__ __nv_bfloat16 g_Ahi[(size_t)NN * 1024];
__device__ __nv_bfloat16 g_Alo[(size_t)NN * 1024];
__device__ __nv_bfloat16 g_Bhi[(size_t)NN * 1024];
__device__ __nv_bfloat16 g_Blo[(size_t)NN * 1024];
__device__ __nv_bfloat16 g_Whi[1 << 20];
__device__ __nv_bfloat16 g_Wlo[1 << 20];
__device__ float g_gsum[NG * 4];
__device__ int   g_gcnt[NG];

__device__ __forceinline__ uint32_t smem_u32(const void* p) {
    uint32_t a;
    asm("{ .reg .u64 t; cvta.to.shared.u64 t, %1; cvt.u32.u64 %0, t; }" : "=r"(a) : "l"(p));
    return a;
}

// ================= graph preprocessing =================
__global__ void zero_kernel() {
    int i = blockIdx.x * blockDim.x + threadIdx.x;
    if (i < NN) g_cnt[i] = 0;
    if (i < NG * 4) g_gsum[i] = 0.f;
    if (i < NG) g_gcnt[i] = 0;
}

__global__ void hist_kernel(const int* __restrict__ dst) {
    int e = blockIdx.x * blockDim.x + threadIdx.x;
    if (e < NE) atomicAdd(&g_cnt[dst[e]], 1);
}

__global__ void invsqrt_kernel() {
    int i = blockIdx.x * blockDim.x + threadIdx.x;
    if (i < NN) g_is[i] = rsqrtf((float)(g_cnt[i] + 1));
}

// ---- 3-kernel parallel scan ----
__global__ void scan1_kernel() {
    int i = blockIdx.x * 256 + threadIdx.x;
    int v = (i < NN) ? g_cnt[i] : 0;
#pragma unroll
    for (int o = 16; o > 0; o >>= 1) v += __shfl_down_sync(0xffffffffu, v, o);
    __shared__ int ws[8];
    if ((threadIdx.x & 31) == 0) ws[threadIdx.x >> 5] = v;
    __syncthreads();
    if (threadIdx.x < 8) {
        int s = ws[threadIdx.x];
#pragma unroll
        for (int o = 4; o > 0; o >>= 1) s += __shfl_down_sync(0xffu, s, o);
        if (threadIdx.x == 0) g_bsum[blockIdx.x] = s;
    }
}

__global__ void scan2_kernel() {   // 1 block, 512 threads: exclusive scan of block sums
    int tid = threadIdx.x;
    int v = (tid < NBLK) ? g_bsum[tid] : 0;
    __shared__ int sm[512];
    sm[tid] = v;
    __syncthreads();
    for (int o = 1; o < 512; o <<= 1) {
        int a = (tid >= o) ? sm[tid - o] : 0;
        __syncthreads();
        sm[tid] += a;
        __syncthreads();
    }
    if (tid < NBLK) g_bsum[tid] = sm[tid] - v;
    if (tid == NBLK - 1) g_rowptr[NN] = sm[tid];
}

__global__ void scan3_kernel() {
    int i = blockIdx.x * 256 + threadIdx.x;
    int v = (i < NN) ? g_cnt[i] : 0;
    int lane = threadIdx.x & 31, w = threadIdx.x >> 5;
    int x = v;
#pragma unroll
    for (int o = 1; o < 32; o <<= 1) {
        int t = __shfl_up_sync(0xffffffffu, x, o);
        if (lane >= o) x += t;
    }
    __shared__ int ws[8];
    if (lane == 31) ws[w] = x;
    __syncthreads();
    if (threadIdx.x < 8) {
        int s = ws[threadIdx.x];
#pragma unroll
        for (int o = 1; o < 8; o <<= 1) {
            int t = __shfl_up_sync(0xffu, s, o);
            if ((int)threadIdx.x >= o) s += t;
        }
        ws[threadIdx.x] = s;
    }
    __syncthreads();
    int excl = x - v + (w ? ws[w - 1] : 0) + g_bsum[blockIdx.x];
    if (i < NN) {
        g_rowptr[i] = excl;
        g_cursor[i] = excl;
    }
}

__global__ void csr_fill_kernel(const int* __restrict__ src, const int* __restrict__ dst) {
    int e = blockIdx.x * blockDim.x + threadIdx.x;
    if (e >= NE) return;
    int d = dst[e];
    int s = src[e];
    int p = atomicAdd(&g_cursor[d], 1);
    g_col[p] = s;
    g_wgt[p] = g_is[s] * g_is[d];
}

// ================= aggregation =================
template <int H>
__global__ void agg_kernel(const float* __restrict__ h, float* __restrict__ out) {
    const int node = blockIdx.x * 4 + (threadIdx.x >> 5);
    if (node >= NN) return;
    const int lane = threadIdx.x & 31;
    constexpr int V = H / 128;

    float4 acc[V];
    float self = g_is[node];
    self = self * self;
    const float4* hrow = (const float4*)(h + (size_t)node * H);
#pragma unroll
    for (int v = 0; v < V; v++) {
        float4 t = hrow[lane + 32 * v];
        acc[v] = make_float4(t.x * self, t.y * self, t.z * self, t.w * self);
    }
    const int beg = g_rowptr[node];
    const int end = g_rowptr[node + 1];
    for (int p = beg; p < end; p++) {
        int s = g_col[p];
        float w = g_wgt[p];
        const float4* sr = (const float4*)(h + (size_t)s * H);
#pragma unroll
        for (int v = 0; v < V; v++) {
            float4 t = sr[lane + 32 * v];
            acc[v].x += w * t.x; acc[v].y += w * t.y;
            acc[v].z += w * t.z; acc[v].w += w * t.w;
        }
    }
    float4* orow = (float4*)(out + (size_t)node * H);
#pragma unroll
    for (int v = 0; v < V; v++) orow[lane + 32 * v] = acc[v];
}

// ================= fp32 -> hi/lo bf16 plane conversion =================
__global__ void wconv_kernel(const float* __restrict__ W, int K, int N) {
    int idx = blockIdx.x * blockDim.x + threadIdx.x;
    if (idx >= N * K) return;
    int n = idx / K, k = idx - n * K;
    float v = W[(size_t)k * N + n];    // transpose to N-major
    __nv_bfloat16 hi = __float2bfloat16(v);
    g_Whi[idx] = hi;
    g_Wlo[idx] = __float2bfloat16(v - __bfloat162float(hi));
}

__global__ void aconv_kernel(const float* __restrict__ A, __nv_bfloat16* __restrict__ hi,
                             __nv_bfloat16* __restrict__ lo, size_t total) {
    size_t i = blockIdx.x * (size_t)blockDim.x + threadIdx.x;
    if (i >= total) return;
    float v = A[i];
    __nv_bfloat16 h = __float2bfloat16(v);
    hi[i] = h;
    lo[i] = __float2bfloat16(v - __bfloat162float(h));
}

// ================= tensor-core GEMM: C = act(A @ W^T + b) with hi/lo planes ====
// A planes [M,K], W planes [N,K]. CTA tile 128 x BN, BK=32, 3-stage cp.async.
// 8 warps: 2 (M) x 4 (N); warp tile 64 x (BN/4).
#define MMA_BF16(ACC, AF, B0, B1)                                                \
    asm volatile(                                                                \
        "mma.sync.aligned.m16n8k16.row.col.f32.bf16.bf16.f32 "                   \
        "{%0,%1,%2,%3}, {%4,%5,%6,%7}, {%8,%9}, {%0,%1,%2,%3};"                  \
        : "+f"((ACC)[0]), "+f"((ACC)[1]), "+f"((ACC)[2]), "+f"((ACC)[3])         \
        : "r"((AF)[0]), "r"((AF)[1]), "r"((AF)[2]), "r"((AF)[3]),                \
          "r"(B0), "r"(B1))

template <int BN, int OUTMODE>  // OUTMODE 0: fp32 out; 1: hi/lo bf16 planes out
__global__ __launch_bounds__(256) void gemm_mma(
    const __nv_bfloat16* __restrict__ Ahi, const __nv_bfloat16* __restrict__ Alo,
    const __nv_bfloat16* __restrict__ Whi, const __nv_bfloat16* __restrict__ Wlo,
    const float* __restrict__ bias, int M, int K, int N, int relu,
    float* __restrict__ outF, __nv_bfloat16* __restrict__ outHi,
    __nv_bfloat16* __restrict__ outLo) {
    constexpr int NA = BN / 32;                 // n8-atoms per warp
    constexpr int STAGE_A = 128 * 64 * 2;       // hi+lo planes, 64B rows
    constexpr int STAGE_B = BN * 64 * 2;
    constexpr int STAGE = STAGE_A + STAGE_B;

    extern __shared__ char dynsm[];
    const uint32_t base0 = (smem_u32(dynsm) + 1023u) & ~1023u;

    const int tid = threadIdx.x;
    const int lane = tid & 31, wid = tid >> 5;
    const int wm = wid & 1, wn = wid >> 1;
    const int m0 = blockIdx.y * 128, n0 = blockIdx.x * BN;
    const int nch = K >> 5;

    float acc[4][NA][4];
#pragma unroll
    for (int i = 0; i < 4; i++)
#pragma unroll
        for (int j = 0; j < NA; j++)
#pragma unroll
            for (int q = 0; q < 4; q++) acc[i][j][q] = 0.f;

    auto fill = [&](int ci, int buf) {
        const int kb = ci * 64;   // byte offset along K row
        const uint32_t st = base0 + buf * STAGE;
#pragma unroll
        for (int p = 0; p < 2; p++) {
            const __nv_bfloat16* Ap = p ? Alo : Ahi;
            const uint32_t dA = st + p * 8192;
#pragma unroll
            for (int i = 0; i < 2; i++) {
                int t2 = tid + i * 256;
                int r = t2 >> 2, c = t2 & 3;
                int row = m0 + r;
                int rowc = (row < M) ? row : (M - 1);
                const char* src = (const char*)(Ap + (size_t)rowc * K) + kb + c * 16;
                uint32_t ssize = (row < M) ? 16u : 0u;
                uint32_t dst = dA + (uint32_t)(r * 64 + ((c ^ ((r >> 1) & 3)) * 16));
                asm volatile("cp.async.cg.shared.global [%0], [%1], 16, %2;"
                             :: "r"(dst), "l"(src), "r"(ssize) : "memory");
            }
        }
#pragma unroll
        for (int p = 0; p < 2; p++) {
            const __nv_bfloat16* Wp = p ? Wlo : Whi;
            const uint32_t dB = st + STAGE_A + p * (BN * 64);
#pragma unroll
            for (int i = 0; i < BN / 64; i++) {
                int t2 = tid + i * 256;
                int r = t2 >> 2, c = t2 & 3;
                const char* src = (const char*)(Wp + (size_t)(n0 + r) * K) + kb + c * 16;
                uint32_t dst = dB + (uint32_t)(r * 64 + ((c ^ ((r >> 1) & 3)) * 16));
                asm volatile("cp.async.cg.shared.global [%0], [%1], 16;"
                             :: "r"(dst), "l"(src) : "memory");
            }
        }
        asm volatile("cp.async.commit_group;" ::: "memory");
    };

    auto compute = [&](int buf) {
        const uint32_t st = base0 + buf * STAGE;
        const uint32_t aHiB = st, aLoB = st + 8192;
        const uint32_t bHiB = st + STAGE_A, bLoB = st + STAGE_A + BN * 64;
#pragma unroll
        for (int ks = 0; ks < 2; ks++) {
            uint32_t ah[4][4], al[4][4];
#pragma unroll
            for (int ma = 0; ma < 4; ma++) {
                int r = wm * 64 + ma * 16 + (lane & 15);
                int c = ks * 2 + (lane >> 4);
                uint32_t off = (uint32_t)(r * 64 + ((c ^ ((r >> 1) & 3)) * 16));
                asm volatile("ldmatrix.sync.aligned.m8n8.x4.shared.b16 {%0,%1,%2,%3}, [%4];"
                             : "=r"(ah[ma][0]), "=r"(ah[ma][1]), "=r"(ah[ma][2]), "=r"(ah[ma][3])
                             : "r"(aHiB + off));
                asm volatile("ldmatrix.sync.aligned.m8n8.x4.shared.b16 {%0,%1,%2,%3}, [%4];"
                             : "=r"(al[ma][0]), "=r"(al[ma][1]), "=r"(al[ma][2]), "=r"(al[ma][3])
                             : "r"(aLoB + off));
            }
#pragma unroll
            for (int nb = 0; nb < NA / 2; nb++) {
                int r = wn * (BN / 4) + nb * 16 + (lane & 7) + ((lane >> 4) & 1) * 8;
                int c = ks * 2 + ((lane >> 3) & 1);
                uint32_t off = (uint32_t)(r * 64 + ((c ^ ((r >> 1) & 3)) * 16));
                uint32_t b0, b1, b2, b3;
                asm volatile("ldmatrix.sync.aligned.m8n8.x4.shared.b16 {%0,%1,%2,%3}, [%4];"
                             : "=r"(b0), "=r"(b1), "=r"(b2), "=r"(b3) : "r"(bHiB + off));
#pragma unroll
                for (int ma = 0; ma < 4; ma++) {
                    MMA_BF16(acc[ma][nb * 2], ah[ma], b0, b1);
                    MMA_BF16(acc[ma][nb * 2 + 1], ah[ma], b2, b3);
                    MMA_BF16(acc[ma][nb * 2], al[ma], b0, b1);
                    MMA_BF16(acc[ma][nb * 2 + 1], al[ma], b2, b3);
                }
                asm volatile("ldmatrix.sync.aligned.m8n8.x4.shared.b16 {%0,%1,%2,%3}, [%4];"
                             : "=r"(b0), "=r"(b1), "=r"(b2), "=r"(b3) : "r"(bLoB + off));
#pragma unroll
                for (int ma = 0; ma < 4; ma++) {
                    MMA_BF16(acc[ma][nb * 2], ah[ma], b0, b1);
                    MMA_BF16(acc[ma][nb * 2 + 1], ah[ma], b2, b3);
                }
            }
        }
    };

    fill(0, 0);
    fill(1, 1);
    for (int ci = 0; ci < nch; ci++) {
        if (ci + 1 < nch) {
            asm volatile("cp.async.wait_group 1;" ::: "memory");
        } else {
            asm volatile("cp.async.wait_group 0;" ::: "memory");
        }
        __syncthreads();
        if (ci + 2 < nch) fill(ci + 2, (ci + 2) % 3);
        compute(ci % 3);
    }

    // ---- epilogue ----
#pragma unroll
    for (int ma = 0; ma < 4; ma++) {
        int r0 = m0 + wm * 64 + ma * 16 + (lane >> 2);
#pragma unroll
        for (int na = 0; na < NA; na++) {
            int c = n0 + wn * (BN / 4) + na * 8 + (lane & 3) * 2;
            float b0v = __ldg(bias + c), b1v = __ldg(bias + c + 1);
            float v00 = acc[ma][na][0] + b0v, v01 = acc[ma][na][1] + b1v;
            float v10 = acc[ma][na][2] + b0v, v11 = acc[ma][na][3] + b1v;
            if (relu) {
                v00 = fmaxf(v00, 0.f); v01 = fmaxf(v01, 0.f);
                v10 = fmaxf(v10, 0.f); v11 = fmaxf(v11, 0.f);
            }
            if (OUTMODE == 0) {
                if (r0 < M) *(float2*)(outF + (size_t)r0 * N + c) = make_float2(v00, v01);
                if (r0 + 8 < M) *(float2*)(outF + (size_t)(r0 + 8) * N + c) = make_float2(v10, v11);
            } else {
#pragma unroll
                for (int rr = 0; rr < 2; rr++) {
                    int row = r0 + rr * 8;
                    if (row >= M) continue;
                    float va = rr ? v10 : v00, vb = rr ? v11 : v01;
                    __nv_bfloat16 h0 = __float2bfloat16(va), h1 = __float2bfloat16(vb);
                    __nv_bfloat16 l0 = __float2bfloat16(va - __bfloat162float(h0));
                    __nv_bfloat16 l1 = __float2bfloat16(vb - __bfloat162float(h1));
                    uint32_t hp = (uint32_t)__bfloat16_as_ushort(h0) |
                                  ((uint32_t)__bfloat16_as_ushort(h1) << 16);
                    uint32_t lp = (uint32_t)__bfloat16_as_ushort(l0) |
                                  ((uint32_t)__bfloat16_as_ushort(l1) << 16);
                    *(uint32_t*)(outHi + (size_t)row * N + c) = hp;
                    *(uint32_t*)(outLo + (size_t)row * N + c) = lp;
                }
            }
        }
    }
}

// ================= final layer (512 -> 4) + pooling =================
__global__ void final_kernel(const float* __restrict__ m2, const float* __restrict__ lw3,
                             const float* __restrict__ lb3, const int* __restrict__ batch) {
    const int node = blockIdx.x * 4 + (threadIdx.x >> 5);
    if (node >= NN) return;
    const int lane = threadIdx.x & 31;
    float a0 = 0.f, a1 = 0.f, a2 = 0.f, a3 = 0.f;
    const float* row = m2 + (size_t)node * 512;
    for (int k = lane; k < 512; k += 32) {
        float v = row[k];
        float4 w = *(const float4*)(lw3 + k * 4);
        a0 += v * w.x; a1 += v * w.y; a2 += v * w.z; a3 += v * w.w;
    }
#pragma unroll
    for (int off = 16; off > 0; off >>= 1) {
        a0 += __shfl_down_sync(0xffffffffu, a0, off);
        a1 += __shfl_down_sync(0xffffffffu, a1, off);
        a2 += __shfl_down_sync(0xffffffffu, a2, off);
        a3 += __shfl_down_sync(0xffffffffu, a3, off);
    }
    if (lane == 0) {
        int g = batch[node];
        atomicAdd(&g_gsum[g * 4 + 0], a0 + lb3[0]);
        atomicAdd(&g_gsum[g * 4 + 1], a1 + lb3[1]);
        atomicAdd(&g_gsum[g * 4 + 2], a2 + lb3[2]);
        atomicAdd(&g_gsum[g * 4 + 3], a3 + lb3[3]);
        atomicAdd(&g_gcnt[g], 1);
    }
}

__global__ void finalize_kernel(float* __restrict__ out) {
    int i = blockIdx.x * blockDim.x + threadIdx.x;
    if (i < NG * 4) {
        float c = fmaxf((float)g_gcnt[i >> 2], 1.f);
        out[i] = g_gsum[i] / c;
    }
}

// ================= launch =================
extern "C" void kernel_launch(void* const* d_in, const int* in_sizes, int n_in,
                              void* d_out, int out_size) {
    const float* x    = (const float*)d_in[0];
    const int*   ei   = (const int*)d_in[1];
    const int*   bat  = (const int*)d_in[2];
    const float* W1   = (const float*)d_in[3];
    const float* b1   = (const float*)d_in[4];
    const float* W2   = (const float*)d_in[5];
    const float* b2   = (const float*)d_in[6];
    const float* W3   = (const float*)d_in[7];
    const float* b3   = (const float*)d_in[8];
    const float* lw1  = (const float*)d_in[9];
    const float* lb1  = (const float*)d_in[10];
    const float* lw2  = (const float*)d_in[11];
    const float* lb2  = (const float*)d_in[12];
    const float* lw3  = (const float*)d_in[13];
    const float* lb3  = (const float*)d_in[14];
    float* out = (float*)d_out;

    const int* src = ei;
    const int* dst = ei + NE;

    float *bufA, *bufB;
    cudaGetSymbolAddress((void**)&bufA, g_bufA);
    cudaGetSymbolAddress((void**)&bufB, g_bufB);
    __nv_bfloat16 *Ahi, *Alo, *Bhi, *Blo, *Whi, *Wlo;
    cudaGetSymbolAddress((void**)&Ahi, g_Ahi);
    cudaGetSymbolAddress((void**)&Alo, g_Alo);
    cudaGetSymbolAddress((void**)&Bhi, g_Bhi);
    cudaGetSymbolAddress((void**)&Blo, g_Blo);
    cudaGetSymbolAddress((void**)&Whi, g_Whi);
    cudaGetSymbolAddress((void**)&Wlo, g_Wlo);

    constexpr int SM128 = 3 * (128 * 64 * 2 + 128 * 64 * 2) + 1024;   //  99328
    constexpr int SM256 = 3 * (128 * 64 * 2 + 256 * 64 * 2) + 1024;   // 148480
    cudaFuncSetAttribute(gemm_mma<128, 0>, cudaFuncAttributeMaxDynamicSharedMemorySize, SM128);
    cudaFuncSetAttribute(gemm_mma<256, 0>, cudaFuncAttributeMaxDynamicSharedMemorySize, SM256);
    cudaFuncSetAttribute(gemm_mma<256, 1>, cudaFuncAttributeMaxDynamicSharedMemorySize, SM256);

    // ---- graph preprocessing ----
    zero_kernel<<<(NN + 255) / 256, 256>>>();
    hist_kernel<<<(NE + 255) / 256, 256>>>(dst);
    invsqrt_kernel<<<(NN + 255) / 256, 256>>>();
    scan1_kernel<<<NBLK, 256>>>();
    scan2_kernel<<<1, 512>>>();
    scan3_kernel<<<NBLK, 256>>>();
    csr_fill_kernel<<<(NE + 255) / 256, 256>>>(src, dst);

    const int aggBlocks = (NN + 3) / 4;
    const int tilesM = (NN + 127) / 128;   // 782

    // ---- layer 1: agg -> split -> mma (K=128, N=128) ----
    agg_kernel<128><<<aggBlocks, 128>>>(x, bufA);
    aconv_kernel<<<(int)(((size_t)NN * 128 + 255) / 256), 256>>>(bufA, Ahi, Alo, (size_t)NN * 128);
    wconv_kernel<<<(128 * 128 + 255) / 256, 256>>>(W1, 128, 128);
    gemm_mma<128, 0><<<dim3(1, tilesM), 256, SM128>>>(Ahi, Alo, Whi, Wlo, b1,
                                                      NN, 128, 128, 1, bufB, nullptr, nullptr);

    // ---- layer 2: agg -> split -> mma (K=128, N=256) ----
    agg_kernel<128><<<aggBlocks, 128>>>(bufB, bufA);
    aconv_kernel<<<(int)(((size_t)NN * 128 + 255) / 256), 256>>>(bufA, Ahi, Alo, (size_t)NN * 128);
    wconv_kernel<<<(256 * 128 + 255) / 256, 256>>>(W2, 128, 256);
    gemm_mma<256, 0><<<dim3(1, tilesM), 256, SM256>>>(Ahi, Alo, Whi, Wlo, b2,
                                                      NN, 128, 256, 1, bufB, nullptr, nullptr);

    // ---- layer 3: agg -> split -> mma (K=256, N=512), split out ----
    agg_kernel<256><<<aggBlocks, 128>>>(bufB, bufA);
    aconv_kernel<<<(int)(((size_t)NN * 256 + 255) / 256), 256>>>(bufA, Ahi, Alo, (size_t)NN * 256);
    wconv_kernel<<<(512 * 256 + 255) / 256, 256>>>(W3, 256, 512);
    gemm_mma<256, 1><<<dim3(2, tilesM), 256, SM256>>>(Ahi, Alo, Whi, Wlo, b3,
                                                      NN, 256, 512, 0, nullptr, Bhi, Blo);

    // ---- MLP1: (K=512, N=1024), split out ----
    wconv_kernel<<<(1024 * 512 + 255) / 256, 256>>>(lw1, 512, 1024);
    gemm_mma<256, 1><<<dim3(4, tilesM), 256, SM256>>>(Bhi, Blo, Whi, Wlo, lb1,
                                                      NN, 512, 1024, 1, nullptr, Ahi, Alo);

    // ---- MLP2: (K=1024, N=512), fp32 out ----
    wconv_kernel<<<(512 * 1024 + 255) / 256, 256>>>(lw2, 1024, 512);
    gemm_mma<256, 0><<<dim3(2, tilesM), 256, SM256>>>(Ahi, Alo, Whi, Wlo, lb2,
                                                      NN, 1024, 512, 1, bufA, nullptr, nullptr);

    // ---- final layer + pooling ----
    final_kernel<<<aggBlocks, 128>>>(bufA, lw3, lb3, bat);
    finalize_kernel<<<(NG * 4 + 255) / 256, 256>>>(out);
}

// round 8
// speedup vs baseline: 3.4155x; 1.3374x over previous
#include <cuda_runtime.h>
#include <cuda_bf16.h>
#include <cuda_fp16.h>
#include <cstdint>

#define NN 100000
#define NE 3200000
#define NG 256
#define NBLK 391   // ceil(NN/256)

// ================= device scratch (no allocations allowed) =================
__device__ int   g_cnt[NN];
__device__ int   g_rowptr[NN + 1];
__device__ int   g_cursor[NN];
__device__ int   g_bsum[NBLK];
__device__ int   g_col[NE];
__device__ float g_wgt[NE];
__device__ float g_is[NN];
__device__ float g_bufB[(size_t)NN * 512];
__device__ __half g_Ahi[(size_t)NN * 1024];
__device__ __half g_Alo[(size_t)NN * 1024];
__device__ __half g_Bhi[(size_t)NN * 1024];
__device__ __half g_Blo[(size_t)NN * 1024];
__device__ __half g_Whi[1 << 20];
__device__ __half g_Wlo[1 << 20];
__device__ float g_nsum[(size_t)NN * 4];
__device__ float g_gsum[NG * 4];
__device__ int   g_gcnt[NG];

__device__ __forceinline__ uint32_t smem_u32(const void* p) {
    uint32_t a;
    asm("{ .reg .u64 t; cvta.to.shared.u64 t, %1; cvt.u32.u64 %0, t; }" : "=r"(a) : "l"(p));
    return a;
}

// ================= graph preprocessing =================
__global__ void zero_kernel() {
    int i = blockIdx.x * blockDim.x + threadIdx.x;
    if (i < NN) g_cnt[i] = 0;
    if (i < NN * 4) g_nsum[i] = 0.f;
    if (i < NG * 4) g_gsum[i] = 0.f;
    if (i < NG) g_gcnt[i] = 0;
}

__global__ void hist_kernel(const int* __restrict__ dst) {
    int e = blockIdx.x * blockDim.x + threadIdx.x;
    if (e < NE) atomicAdd(&g_cnt[dst[e]], 1);
}

__global__ void invsqrt_kernel() {
    int i = blockIdx.x * blockDim.x + threadIdx.x;
    if (i < NN) g_is[i] = rsqrtf((float)(g_cnt[i] + 1));
}

__global__ void scan1_kernel() {
    int i = blockIdx.x * 256 + threadIdx.x;
    int v = (i < NN) ? g_cnt[i] : 0;
#pragma unroll
    for (int o = 16; o > 0; o >>= 1) v += __shfl_down_sync(0xffffffffu, v, o);
    __shared__ int ws[8];
    if ((threadIdx.x & 31) == 0) ws[threadIdx.x >> 5] = v;
    __syncthreads();
    if (threadIdx.x < 8) {
        int s = ws[threadIdx.x];
#pragma unroll
        for (int o = 4; o > 0; o >>= 1) s += __shfl_down_sync(0xffu, s, o);
        if (threadIdx.x == 0) g_bsum[blockIdx.x] = s;
    }
}

__global__ void scan2_kernel() {
    int tid = threadIdx.x;
    int v = (tid < NBLK) ? g_bsum[tid] : 0;
    __shared__ int sm[512];
    sm[tid] = v;
    __syncthreads();
    for (int o = 1; o < 512; o <<= 1) {
        int a = (tid >= o) ? sm[tid - o] : 0;
        __syncthreads();
        sm[tid] += a;
        __syncthreads();
    }
    if (tid < NBLK) g_bsum[tid] = sm[tid] - v;
    if (tid == NBLK - 1) g_rowptr[NN] = sm[tid];
}

__global__ void scan3_kernel() {
    int i = blockIdx.x * 256 + threadIdx.x;
    int v = (i < NN) ? g_cnt[i] : 0;
    int lane = threadIdx.x & 31, w = threadIdx.x >> 5;
    int x = v;
#pragma unroll
    for (int o = 1; o < 32; o <<= 1) {
        int t = __shfl_up_sync(0xffffffffu, x, o);
        if (lane >= o) x += t;
    }
    __shared__ int ws[8];
    if (lane == 31) ws[w] = x;
    __syncthreads();
    if (threadIdx.x < 8) {
        int s = ws[threadIdx.x];
#pragma unroll
        for (int o = 1; o < 8; o <<= 1) {
            int t = __shfl_up_sync(0xffu, s, o);
            if ((int)threadIdx.x >= o) s += t;
        }
        ws[threadIdx.x] = s;
    }
    __syncthreads();
    int excl = x - v + (w ? ws[w - 1] : 0) + g_bsum[blockIdx.x];
    if (i < NN) {
        g_rowptr[i] = excl;
        g_cursor[i] = excl;
    }
}

__global__ void csr_fill_kernel(const int* __restrict__ src, const int* __restrict__ dst) {
    int e = blockIdx.x * blockDim.x + threadIdx.x;
    if (e >= NE) return;
    int d = dst[e];
    int s = src[e];
    int p = atomicAdd(&g_cursor[d], 1);
    g_col[p] = s;
    g_wgt[p] = g_is[s] * g_is[d];
}

// ================= aggregation (optionally emits fp16 hi/lo planes) =========
template <int H, int OSPLIT>
__global__ void agg_kernel(const float* __restrict__ h, float* __restrict__ outF,
                           __half* __restrict__ outHi, __half* __restrict__ outLo) {
    const int node = blockIdx.x * 4 + (threadIdx.x >> 5);
    if (node >= NN) return;
    const int lane = threadIdx.x & 31;
    constexpr int V = H / 128;

    float4 acc[V];
    float self = g_is[node];
    self = self * self;
    const float4* hrow = (const float4*)(h + (size_t)node * H);
#pragma unroll
    for (int v = 0; v < V; v++) {
        float4 t = hrow[lane + 32 * v];
        acc[v] = make_float4(t.x * self, t.y * self, t.z * self, t.w * self);
    }
    const int beg = g_rowptr[node];
    const int end = g_rowptr[node + 1];
    for (int p = beg; p < end; p++) {
        int s = g_col[p];
        float w = g_wgt[p];
        const float4* sr = (const float4*)(h + (size_t)s * H);
#pragma unroll
        for (int v = 0; v < V; v++) {
            float4 t = sr[lane + 32 * v];
            acc[v].x += w * t.x; acc[v].y += w * t.y;
            acc[v].z += w * t.z; acc[v].w += w * t.w;
        }
    }
    if (OSPLIT == 0) {
        float4* orow = (float4*)(outF + (size_t)node * H);
#pragma unroll
        for (int v = 0; v < V; v++) orow[lane + 32 * v] = acc[v];
    } else {
#pragma unroll
        for (int v = 0; v < V; v++) {
            float vv[4] = {acc[v].x, acc[v].y, acc[v].z, acc[v].w};
            ushort hs[4], ls[4];
#pragma unroll
            for (int q = 0; q < 4; q++) {
                __half hh = __float2half_rn(vv[q]);
                hs[q] = __half_as_ushort(hh);
                ls[q] = __half_as_ushort(__float2half_rn(vv[q] - __half2float(hh)));
            }
            uint2 ph = make_uint2((uint32_t)hs[0] | ((uint32_t)hs[1] << 16),
                                  (uint32_t)hs[2] | ((uint32_t)hs[3] << 16));
            uint2 pl = make_uint2((uint32_t)ls[0] | ((uint32_t)ls[1] << 16),
                                  (uint32_t)ls[2] | ((uint32_t)ls[3] << 16));
            ((uint2*)(outHi + (size_t)node * H))[lane + 32 * v] = ph;
            ((uint2*)(outLo + (size_t)node * H))[lane + 32 * v] = pl;
        }
    }
}

// ================= fp32 -> fp16 hi/lo weight conversion (transposed) =========
__global__ void wconv_kernel(const float* __restrict__ W, int K, int N, int both) {
    int idx = blockIdx.x * blockDim.x + threadIdx.x;
    if (idx >= N * K) return;
    int n = idx / K, k = idx - n * K;
    float v = W[(size_t)k * N + n];
    __half hi = __float2half_rn(v);
    g_Whi[idx] = hi;
    if (both) g_Wlo[idx] = __float2half_rn(v - __half2float(hi));
}

// ================= tensor-core GEMM (fp16 split, mma.sync) ===================
#define MMA_F16(ACC, AF, B0, B1)                                                 \
    asm volatile(                                                                \
        "mma.sync.aligned.m16n8k16.row.col.f32.f16.f16.f32 "                     \
        "{%0,%1,%2,%3}, {%4,%5,%6,%7}, {%8,%9}, {%0,%1,%2,%3};"                  \
        : "+f"((ACC)[0]), "+f"((ACC)[1]), "+f"((ACC)[2]), "+f"((ACC)[3])         \
        : "r"((AF)[0]), "r"((AF)[1]), "r"((AF)[2]), "r"((AF)[3]),                \
          "r"(B0), "r"(B1))

// OUTMODE 0: fp32 out. 1: fp16 hi/lo plane out. 2: fused 512->4 dot + node-sum.
// NPROD 3: (Ahi+Alo)(Whi+Wlo) minus lolo. NPROD 2: (Ahi+Alo)*Whi only.
template <int BN, int NPROD, int OUTMODE>
__global__ __launch_bounds__(256) void gemm_mma(
    const __half* __restrict__ Ahi, const __half* __restrict__ Alo,
    const __half* __restrict__ Whi, const __half* __restrict__ Wlo,
    const float* __restrict__ bias, int M, int K, int N, int relu,
    float* __restrict__ outF, __half* __restrict__ outHi, __half* __restrict__ outLo,
    const float* __restrict__ lw3, float* __restrict__ nsum) {
    constexpr int NA = BN / 32;
    constexpr int STAGE_A = 128 * 64 * 2;
    constexpr int STAGE_B = BN * 64 * (NPROD == 3 ? 2 : 1);
    constexpr int STAGE = STAGE_A + STAGE_B;

    extern __shared__ char dynsm[];
    const uint32_t base0 = (smem_u32(dynsm) + 1023u) & ~1023u;

    const int tid = threadIdx.x;
    const int lane = tid & 31, wid = tid >> 5;
    const int wm = wid & 1, wn = wid >> 1;
    const int m0 = blockIdx.y * 128, n0 = blockIdx.x * BN;
    const int nch = K >> 5;

    float acc[4][NA][4];
#pragma unroll
    for (int i = 0; i < 4; i++)
#pragma unroll
        for (int j = 0; j < NA; j++)
#pragma unroll
            for (int q = 0; q < 4; q++) acc[i][j][q] = 0.f;

    auto fill = [&](int ci, int buf) {
        const int kb = ci * 64;
        const uint32_t st = base0 + buf * STAGE;
#pragma unroll
        for (int p = 0; p < 2; p++) {
            const __half* Ap = p ? Alo : Ahi;
            const uint32_t dA = st + p * 8192;
#pragma unroll
            for (int i = 0; i < 2; i++) {
                int t2 = tid + i * 256;
                int r = t2 >> 2, c = t2 & 3;
                int row = m0 + r;
                int rowc = (row < M) ? row : (M - 1);
                const char* src = (const char*)(Ap + (size_t)rowc * K) + kb + c * 16;
                uint32_t ssize = (row < M) ? 16u : 0u;
                uint32_t dst = dA + (uint32_t)(r * 64 + ((c ^ ((r >> 1) & 3)) * 16));
                asm volatile("cp.async.cg.shared.global [%0], [%1], 16, %2;"
                             :: "r"(dst), "l"(src), "r"(ssize) : "memory");
            }
        }
#pragma unroll
        for (int p = 0; p < (NPROD == 3 ? 2 : 1); p++) {
            const __half* Wp = p ? Wlo : Whi;
            const uint32_t dB = st + STAGE_A + p * (BN * 64);
#pragma unroll
            for (int i = 0; i < BN / 64; i++) {
                int t2 = tid + i * 256;
                int r = t2 >> 2, c = t2 & 3;
                const char* src = (const char*)(Wp + (size_t)(n0 + r) * K) + kb + c * 16;
                uint32_t dst = dB + (uint32_t)(r * 64 + ((c ^ ((r >> 1) & 3)) * 16));
                asm volatile("cp.async.cg.shared.global [%0], [%1], 16;"
                             :: "r"(dst), "l"(src) : "memory");
            }
        }
        asm volatile("cp.async.commit_group;" ::: "memory");
    };

    auto compute = [&](int buf) {
        const uint32_t st = base0 + buf * STAGE;
        const uint32_t aHiB = st, aLoB = st + 8192;
        const uint32_t bHiB = st + STAGE_A, bLoB = st + STAGE_A + BN * 64;
#pragma unroll
        for (int ks = 0; ks < 2; ks++) {
            uint32_t ah[4][4], al[4][4];
#pragma unroll
            for (int ma = 0; ma < 4; ma++) {
                int r = wm * 64 + ma * 16 + (lane & 15);
                int c = ks * 2 + (lane >> 4);
                uint32_t off = (uint32_t)(r * 64 + ((c ^ ((r >> 1) & 3)) * 16));
                asm volatile("ldmatrix.sync.aligned.m8n8.x4.shared.b16 {%0,%1,%2,%3}, [%4];"
                             : "=r"(ah[ma][0]), "=r"(ah[ma][1]), "=r"(ah[ma][2]), "=r"(ah[ma][3])
                             : "r"(aHiB + off));
                asm volatile("ldmatrix.sync.aligned.m8n8.x4.shared.b16 {%0,%1,%2,%3}, [%4];"
                             : "=r"(al[ma][0]), "=r"(al[ma][1]), "=r"(al[ma][2]), "=r"(al[ma][3])
                             : "r"(aLoB + off));
            }
#pragma unroll
            for (int nb = 0; nb < NA / 2; nb++) {
                int r = wn * (BN / 4) + nb * 16 + (lane & 7) + ((lane >> 4) & 1) * 8;
                int c = ks * 2 + ((lane >> 3) & 1);
                uint32_t off = (uint32_t)(r * 64 + ((c ^ ((r >> 1) & 3)) * 16));
                uint32_t b0, b1, b2, b3;
                asm volatile("ldmatrix.sync.aligned.m8n8.x4.shared.b16 {%0,%1,%2,%3}, [%4];"
                             : "=r"(b0), "=r"(b1), "=r"(b2), "=r"(b3) : "r"(bHiB + off));
#pragma unroll
                for (int ma = 0; ma < 4; ma++) {
                    MMA_F16(acc[ma][nb * 2], ah[ma], b0, b1);
                    MMA_F16(acc[ma][nb * 2 + 1], ah[ma], b2, b3);
                    MMA_F16(acc[ma][nb * 2], al[ma], b0, b1);
                    MMA_F16(acc[ma][nb * 2 + 1], al[ma], b2, b3);
                }
                if (NPROD == 3) {
                    asm volatile("ldmatrix.sync.aligned.m8n8.x4.shared.b16 {%0,%1,%2,%3}, [%4];"
                                 : "=r"(b0), "=r"(b1), "=r"(b2), "=r"(b3) : "r"(bLoB + off));
#pragma unroll
                    for (int ma = 0; ma < 4; ma++) {
                        MMA_F16(acc[ma][nb * 2], ah[ma], b0, b1);
                        MMA_F16(acc[ma][nb * 2 + 1], ah[ma], b2, b3);
                    }
                }
            }
        }
    };

    fill(0, 0);
    fill(1, 1);
    for (int ci = 0; ci < nch; ci++) {
        if (ci + 1 < nch) {
            asm volatile("cp.async.wait_group 1;" ::: "memory");
        } else {
            asm volatile("cp.async.wait_group 0;" ::: "memory");
        }
        __syncthreads();
        if (ci + 2 < nch) fill(ci + 2, (ci + 2) % 3);
        compute(ci % 3);
    }

    // ---- epilogue ----
#pragma unroll
    for (int ma = 0; ma < 4; ma++) {
        int r0 = m0 + wm * 64 + ma * 16 + (lane >> 2);
        float p0[4] = {0.f, 0.f, 0.f, 0.f}, p1[4] = {0.f, 0.f, 0.f, 0.f};
#pragma unroll
        for (int na = 0; na < NA; na++) {
            int c = n0 + wn * (BN / 4) + na * 8 + (lane & 3) * 2;
            float b0v = __ldg(bias + c), b1v = __ldg(bias + c + 1);
            float v00 = acc[ma][na][0] + b0v, v01 = acc[ma][na][1] + b1v;
            float v10 = acc[ma][na][2] + b0v, v11 = acc[ma][na][3] + b1v;
            if (relu) {
                v00 = fmaxf(v00, 0.f); v01 = fmaxf(v01, 0.f);
                v10 = fmaxf(v10, 0.f); v11 = fmaxf(v11, 0.f);
            }
            if (OUTMODE == 0) {
                if (r0 < M) *(float2*)(outF + (size_t)r0 * N + c) = make_float2(v00, v01);
                if (r0 + 8 < M) *(float2*)(outF + (size_t)(r0 + 8) * N + c) = make_float2(v10, v11);
            } else if (OUTMODE == 1) {
#pragma unroll
                for (int rr = 0; rr < 2; rr++) {
                    int row = r0 + rr * 8;
                    if (row >= M) continue;
                    float va = rr ? v10 : v00, vb = rr ? v11 : v01;
                    __half h0 = __float2half_rn(va), h1 = __float2half_rn(vb);
                    __half l0 = __float2half_rn(va - __half2float(h0));
                    __half l1 = __float2half_rn(vb - __half2float(h1));
                    uint32_t hp = (uint32_t)__half_as_ushort(h0) |
                                  ((uint32_t)__half_as_ushort(h1) << 16);
                    uint32_t lp = (uint32_t)__half_as_ushort(l0) |
                                  ((uint32_t)__half_as_ushort(l1) << 16);
                    *(uint32_t*)(outHi + (size_t)row * N + c) = hp;
                    *(uint32_t*)(outLo + (size_t)row * N + c) = lp;
                }
            } else {
                float4 w0 = __ldg((const float4*)(lw3 + c * 4));
                float4 w1 = __ldg((const float4*)(lw3 + (c + 1) * 4));
                p0[0] += v00 * w0.x + v01 * w1.x;  p0[1] += v00 * w0.y + v01 * w1.y;
                p0[2] += v00 * w0.z + v01 * w1.z;  p0[3] += v00 * w0.w + v01 * w1.w;
                p1[0] += v10 * w0.x + v11 * w1.x;  p1[1] += v10 * w0.y + v11 * w1.y;
                p1[2] += v10 * w0.z + v11 * w1.z;  p1[3] += v10 * w0.w + v11 * w1.w;
            }
        }
        if (OUTMODE == 2) {
#pragma unroll
            for (int j = 0; j < 4; j++) {
                p0[j] += __shfl_down_sync(0xffffffffu, p0[j], 2);
                p0[j] += __shfl_down_sync(0xffffffffu, p0[j], 1);
                p1[j] += __shfl_down_sync(0xffffffffu, p1[j], 2);
                p1[j] += __shfl_down_sync(0xffffffffu, p1[j], 1);
            }
            if ((lane & 3) == 0) {
                if (r0 < M) {
#pragma unroll
                    for (int j = 0; j < 4; j++) atomicAdd(&nsum[(size_t)r0 * 4 + j], p0[j]);
                }
                if (r0 + 8 < M) {
#pragma unroll
                    for (int j = 0; j < 4; j++) atomicAdd(&nsum[(size_t)(r0 + 8) * 4 + j], p1[j]);
                }
            }
        }
    }
}

// ================= pooling (warp-aggregated) =================
__global__ void pool_kernel(const int* __restrict__ batch) {
    int i = blockIdx.x * 256 + threadIdx.x;
    int lane = threadIdx.x & 31;
    bool valid = i < NN;
    int g = valid ? batch[i] : -1;
    float4 v = valid ? *(const float4*)(g_nsum + (size_t)i * 4)
                     : make_float4(0.f, 0.f, 0.f, 0.f);
    int g0 = __shfl_sync(0xffffffffu, g, 0);
    bool uni = __all_sync(0xffffffffu, valid && g == g0);
    if (uni) {
#pragma unroll
        for (int o = 16; o > 0; o >>= 1) {
            v.x += __shfl_down_sync(0xffffffffu, v.x, o);
            v.y += __shfl_down_sync(0xffffffffu, v.y, o);
            v.z += __shfl_down_sync(0xffffffffu, v.z, o);
            v.w += __shfl_down_sync(0xffffffffu, v.w, o);
        }
        if (lane == 0) {
            atomicAdd(&g_gsum[g0 * 4 + 0], v.x);
            atomicAdd(&g_gsum[g0 * 4 + 1], v.y);
            atomicAdd(&g_gsum[g0 * 4 + 2], v.z);
            atomicAdd(&g_gsum[g0 * 4 + 3], v.w);
            atomicAdd(&g_gcnt[g0], 32);
        }
    } else if (valid) {
        atomicAdd(&g_gsum[g * 4 + 0], v.x);
        atomicAdd(&g_gsum[g * 4 + 1], v.y);
        atomicAdd(&g_gsum[g * 4 + 2], v.z);
        atomicAdd(&g_gsum[g * 4 + 3], v.w);
        atomicAdd(&g_gcnt[g], 1);
    }
}

__global__ void finalize_kernel(float* __restrict__ out, const float* __restrict__ lb3) {
    int i = blockIdx.x * blockDim.x + threadIdx.x;
    if (i < NG * 4) {
        int cnt = g_gcnt[i >> 2];
        out[i] = (cnt > 0) ? (g_gsum[i] / (float)cnt + lb3[i & 3]) : 0.f;
    }
}

// ================= launch =================
extern "C" void kernel_launch(void* const* d_in, const int* in_sizes, int n_in,
                              void* d_out, int out_size) {
    const float* x    = (const float*)d_in[0];
    const int*   ei   = (const int*)d_in[1];
    const int*   bat  = (const int*)d_in[2];
    const float* W1   = (const float*)d_in[3];
    const float* b1   = (const float*)d_in[4];
    const float* W2   = (const float*)d_in[5];
    const float* b2   = (const float*)d_in[6];
    const float* W3   = (const float*)d_in[7];
    const float* b3   = (const float*)d_in[8];
    const float* lw1  = (const float*)d_in[9];
    const float* lb1  = (const float*)d_in[10];
    const float* lw2  = (const float*)d_in[11];
    const float* lb2  = (const float*)d_in[12];
    const float* lw3  = (const float*)d_in[13];
    const float* lb3  = (const float*)d_in[14];
    float* out = (float*)d_out;

    const int* src = ei;
    const int* dst = ei + NE;

    float *bufB, *nsum;
    cudaGetSymbolAddress((void**)&bufB, g_bufB);
    cudaGetSymbolAddress((void**)&nsum, g_nsum);
    __half *Ahi, *Alo, *Bhi, *Blo, *Whi, *Wlo;
    cudaGetSymbolAddress((void**)&Ahi, g_Ahi);
    cudaGetSymbolAddress((void**)&Alo, g_Alo);
    cudaGetSymbolAddress((void**)&Bhi, g_Bhi);
    cudaGetSymbolAddress((void**)&Blo, g_Blo);
    cudaGetSymbolAddress((void**)&Whi, g_Whi);
    cudaGetSymbolAddress((void**)&Wlo, g_Wlo);

    constexpr int SM_128_3 = 3 * (16384 + 128 * 64 * 2) + 1024;  //  99328
    constexpr int SM_256_3 = 3 * (16384 + 256 * 64 * 2) + 1024;  // 148480
    constexpr int SM_256_2 = 3 * (16384 + 256 * 64) + 1024;      //  99328
    cudaFuncSetAttribute(gemm_mma<128, 3, 0>, cudaFuncAttributeMaxDynamicSharedMemorySize, SM_128_3);
    cudaFuncSetAttribute(gemm_mma<256, 3, 0>, cudaFuncAttributeMaxDynamicSharedMemorySize, SM_256_3);
    cudaFuncSetAttribute(gemm_mma<256, 3, 1>, cudaFuncAttributeMaxDynamicSharedMemorySize, SM_256_3);
    cudaFuncSetAttribute(gemm_mma<256, 2, 1>, cudaFuncAttributeMaxDynamicSharedMemorySize, SM_256_2);
    cudaFuncSetAttribute(gemm_mma<256, 2, 2>, cudaFuncAttributeMaxDynamicSharedMemorySize, SM_256_2);

    // ---- graph preprocessing ----
    zero_kernel<<<(NN * 4 + 255) / 256, 256>>>();
    hist_kernel<<<(NE + 255) / 256, 256>>>(dst);
    invsqrt_kernel<<<(NN + 255) / 256, 256>>>();
    scan1_kernel<<<NBLK, 256>>>();
    scan2_kernel<<<1, 512>>>();
    scan3_kernel<<<NBLK, 256>>>();
    csr_fill_kernel<<<(NE + 255) / 256, 256>>>(src, dst);

    const int aggBlocks = (NN + 3) / 4;
    const int tilesM = (NN + 127) / 128;   // 782

    // ---- layer 1: agg(x) -> split planes -> mma (K=128, N=128) ----
    agg_kernel<128, 1><<<aggBlocks, 128>>>(x, nullptr, Ahi, Alo);
    wconv_kernel<<<(128 * 128 + 255) / 256, 256>>>(W1, 128, 128, 1);
    gemm_mma<128, 3, 0><<<dim3(1, tilesM), 256, SM_128_3>>>(
        Ahi, Alo, Whi, Wlo, b1, NN, 128, 128, 1, bufB, nullptr, nullptr, nullptr, nullptr);

    // ---- layer 2 (K=128, N=256) ----
    agg_kernel<128, 1><<<aggBlocks, 128>>>(bufB, nullptr, Ahi, Alo);
    wconv_kernel<<<(256 * 128 + 255) / 256, 256>>>(W2, 128, 256, 1);
    gemm_mma<256, 3, 0><<<dim3(1, tilesM), 256, SM_256_3>>>(
        Ahi, Alo, Whi, Wlo, b2, NN, 128, 256, 1, bufB, nullptr, nullptr, nullptr, nullptr);

    // ---- layer 3 (K=256, N=512), split out ----
    agg_kernel<256, 1><<<aggBlocks, 128>>>(bufB, nullptr, Ahi, Alo);
    wconv_kernel<<<(512 * 256 + 255) / 256, 256>>>(W3, 256, 512, 1);
    gemm_mma<256, 3, 1><<<dim3(2, tilesM), 256, SM_256_3>>>(
        Ahi, Alo, Whi, Wlo, b3, NN, 256, 512, 0, nullptr, Bhi, Blo, nullptr, nullptr);

    // ---- MLP1 (K=512, N=1024), 2-term, split out ----
    wconv_kernel<<<(1024 * 512 + 255) / 256, 256>>>(lw1, 512, 1024, 0);
    gemm_mma<256, 2, 1><<<dim3(4, tilesM), 256, SM_256_2>>>(
        Bhi, Blo, Whi, nullptr, lb1, NN, 512, 1024, 1, nullptr, Ahi, Alo, nullptr, nullptr);

    // ---- MLP2 (K=1024, N=512), 2-term, fused 512->4 + node-sum ----
    wconv_kernel<<<(512 * 1024 + 255) / 256, 256>>>(lw2, 1024, 512, 0);
    gemm_mma<256, 2, 2><<<dim3(2, tilesM), 256, SM_256_2>>>(
        Ahi, Alo, Whi, nullptr, lb2, NN, 1024, 512, 1, nullptr, nullptr, nullptr, lw3, nsum);

    // ---- pooling ----
    pool_kernel<<<NBLK, 256>>>(bat);
    finalize_kernel<<<(NG * 4 + 255) / 256, 256>>>(out, lb3);
}

// round 9
// speedup vs baseline: 4.9050x; 1.4361x over previous
#include <cuda_runtime.h>
#include <cuda_fp16.h>
#include <cstdint>

#define NN 100000
#define NE 3200000
#define NG 256
#define NBLK 391   // ceil(NN/256)

// ================= device scratch (no allocations allowed) =================
__device__ int   g_cnt[NN];
__device__ int   g_rowptr[NN + 1];
__device__ int   g_cursor[NN];
__device__ int   g_bsum[NBLK];
__device__ int   g_col[NE];
__device__ float g_wgt[NE];
__device__ float g_is[NN];
__device__ __half g_Ahi[(size_t)NN * 256];    // agg output hi plane (max H=256)
__device__ __half g_Alo[(size_t)NN * 256];    // agg output lo plane
__device__ __half g_act1[(size_t)NN * 1024];  // fp16 activation buffer 1
__device__ __half g_act2[(size_t)NN * 1024];  // fp16 activation buffer 2
__device__ __half g_Whi[1 << 20];
__device__ __half g_Wlo[1 << 20];
__device__ float g_nsum[(size_t)NN * 4];
__device__ float g_gsum[NG * 4];
__device__ int   g_gcnt[NG];

__device__ __forceinline__ uint32_t smem_u32(const void* p) {
    uint32_t a;
    asm("{ .reg .u64 t; cvta.to.shared.u64 t, %1; cvt.u32.u64 %0, t; }" : "=r"(a) : "l"(p));
    return a;
}

// ================= graph preprocessing =================
__global__ void zero_kernel() {
    int i = blockIdx.x * blockDim.x + threadIdx.x;
    if (i < NN) g_cnt[i] = 0;
    if (i < NN * 4) g_nsum[i] = 0.f;
    if (i < NG * 4) g_gsum[i] = 0.f;
    if (i < NG) g_gcnt[i] = 0;
}

__global__ void hist_kernel(const int* __restrict__ dst) {
    int e = blockIdx.x * blockDim.x + threadIdx.x;
    if (e < NE) atomicAdd(&g_cnt[dst[e]], 1);
}

__global__ void invsqrt_kernel() {
    int i = blockIdx.x * blockDim.x + threadIdx.x;
    if (i < NN) g_is[i] = rsqrtf((float)(g_cnt[i] + 1));
}

__global__ void scan1_kernel() {
    int i = blockIdx.x * 256 + threadIdx.x;
    int v = (i < NN) ? g_cnt[i] : 0;
#pragma unroll
    for (int o = 16; o > 0; o >>= 1) v += __shfl_down_sync(0xffffffffu, v, o);
    __shared__ int ws[8];
    if ((threadIdx.x & 31) == 0) ws[threadIdx.x >> 5] = v;
    __syncthreads();
    if (threadIdx.x < 8) {
        int s = ws[threadIdx.x];
#pragma unroll
        for (int o = 4; o > 0; o >>= 1) s += __shfl_down_sync(0xffu, s, o);
        if (threadIdx.x == 0) g_bsum[blockIdx.x] = s;
    }
}

__global__ void scan2_kernel() {
    int tid = threadIdx.x;
    int v = (tid < NBLK) ? g_bsum[tid] : 0;
    __shared__ int sm[512];
    sm[tid] = v;
    __syncthreads();
    for (int o = 1; o < 512; o <<= 1) {
        int a = (tid >= o) ? sm[tid - o] : 0;
        __syncthreads();
        sm[tid] += a;
        __syncthreads();
    }
    if (tid < NBLK) g_bsum[tid] = sm[tid] - v;
    if (tid == NBLK - 1) g_rowptr[NN] = sm[tid];
}

__global__ void scan3_kernel() {
    int i = blockIdx.x * 256 + threadIdx.x;
    int v = (i < NN) ? g_cnt[i] : 0;
    int lane = threadIdx.x & 31, w = threadIdx.x >> 5;
    int x = v;
#pragma unroll
    for (int o = 1; o < 32; o <<= 1) {
        int t = __shfl_up_sync(0xffffffffu, x, o);
        if (lane >= o) x += t;
    }
    __shared__ int ws[8];
    if (lane == 31) ws[w] = x;
    __syncthreads();
    if (threadIdx.x < 8) {
        int s = ws[threadIdx.x];
#pragma unroll
        for (int o = 1; o < 8; o <<= 1) {
            int t = __shfl_up_sync(0xffu, s, o);
            if ((int)threadIdx.x >= o) s += t;
        }
        ws[threadIdx.x] = s;
    }
    __syncthreads();
    int excl = x - v + (w ? ws[w - 1] : 0) + g_bsum[blockIdx.x];
    if (i < NN) {
        g_rowptr[i] = excl;
        g_cursor[i] = excl;
    }
}

__global__ void csr_fill_kernel(const int* __restrict__ src, const int* __restrict__ dst) {
    int e = blockIdx.x * blockDim.x + threadIdx.x;
    if (e >= NE) return;
    int d = dst[e];
    int s = src[e];
    int p = atomicAdd(&g_cursor[d], 1);
    g_col[p] = s;
    g_wgt[p] = g_is[s] * g_is[d];
}

// ================= fp32 x -> fp16 plane =================
__global__ void xconv_kernel(const float* __restrict__ x, __half* __restrict__ o, size_t total) {
    size_t i = blockIdx.x * (size_t)blockDim.x + threadIdx.x;
    if (i < total) o[i] = __float2half_rn(x[i]);
}

// ================= aggregation over fp16 planes, fp32 accum, hi/lo split out ==
template <int H>
__global__ void agg16_kernel(const __half* __restrict__ h,
                             __half* __restrict__ outHi, __half* __restrict__ outLo) {
    const int node = blockIdx.x * 4 + (threadIdx.x >> 5);
    if (node >= NN) return;
    const int lane = threadIdx.x & 31;
    constexpr int U = H / 128;   // uint2 (4 halves) per lane

    float acc[U][4];
    float self = g_is[node];
    self = self * self;
    const uint2* hrow = (const uint2*)(h + (size_t)node * H);
#pragma unroll
    for (int u = 0; u < U; u++) {
        uint2 t = hrow[lane + 32 * u];
        float2 a = __half22float2(*(const __half2*)&t.x);
        float2 b = __half22float2(*(const __half2*)&t.y);
        acc[u][0] = self * a.x; acc[u][1] = self * a.y;
        acc[u][2] = self * b.x; acc[u][3] = self * b.y;
    }
    const int beg = g_rowptr[node];
    const int end = g_rowptr[node + 1];
    for (int p = beg; p < end; p++) {
        int s = g_col[p];
        float w = g_wgt[p];
        const uint2* sr = (const uint2*)(h + (size_t)s * H);
#pragma unroll
        for (int u = 0; u < U; u++) {
            uint2 t = sr[lane + 32 * u];
            float2 a = __half22float2(*(const __half2*)&t.x);
            float2 b = __half22float2(*(const __half2*)&t.y);
            acc[u][0] += w * a.x; acc[u][1] += w * a.y;
            acc[u][2] += w * b.x; acc[u][3] += w * b.y;
        }
    }
#pragma unroll
    for (int u = 0; u < U; u++) {
        ushort hs[4], ls[4];
#pragma unroll
        for (int q = 0; q < 4; q++) {
            __half hh = __float2half_rn(acc[u][q]);
            hs[q] = __half_as_ushort(hh);
            ls[q] = __half_as_ushort(__float2half_rn(acc[u][q] - __half2float(hh)));
        }
        uint2 ph = make_uint2((uint32_t)hs[0] | ((uint32_t)hs[1] << 16),
                              (uint32_t)hs[2] | ((uint32_t)hs[3] << 16));
        uint2 pl = make_uint2((uint32_t)ls[0] | ((uint32_t)ls[1] << 16),
                              (uint32_t)ls[2] | ((uint32_t)ls[3] << 16));
        ((uint2*)(outHi + (size_t)node * H))[lane + 32 * u] = ph;
        ((uint2*)(outLo + (size_t)node * H))[lane + 32 * u] = pl;
    }
}

// ================= fp32 -> fp16 hi/lo weight conversion (transposed) =========
__global__ void wconv_kernel(const float* __restrict__ W, int K, int N, int both) {
    int idx = blockIdx.x * blockDim.x + threadIdx.x;
    if (idx >= N * K) return;
    int n = idx / K, k = idx - n * K;
    float v = W[(size_t)k * N + n];
    __half hi = __float2half_rn(v);
    g_Whi[idx] = hi;
    if (both) g_Wlo[idx] = __float2half_rn(v - __half2float(hi));
}

// ================= tensor-core GEMM (fp16, mma.sync) =========================
#define MMA_F16(ACC, AF, B0, B1)                                                 \
    asm volatile(                                                                \
        "mma.sync.aligned.m16n8k16.row.col.f32.f16.f16.f32 "                     \
        "{%0,%1,%2,%3}, {%4,%5,%6,%7}, {%8,%9}, {%0,%1,%2,%3};"                  \
        : "+f"((ACC)[0]), "+f"((ACC)[1]), "+f"((ACC)[2]), "+f"((ACC)[3])         \
        : "r"((AF)[0]), "r"((AF)[1]), "r"((AF)[2]), "r"((AF)[3]),                \
          "r"(B0), "r"(B1))

// NPROD 3: AhiWhi + AloWhi + AhiWlo (hi/lo planes). NPROD 1: pure fp16 AW.
// OUTMODE 0: fp16 plane out. OUTMODE 1: fused 512->4 dot + node-sum.
template <int BN, int NPROD, int OUTMODE>
__global__ __launch_bounds__(256) void gemm_mma(
    const __half* __restrict__ Ahi, const __half* __restrict__ Alo,
    const __half* __restrict__ Whi, const __half* __restrict__ Wlo,
    const float* __restrict__ bias, int M, int K, int N, int relu,
    __half* __restrict__ outH,
    const float* __restrict__ lw3, float* __restrict__ nsum) {
    constexpr int NA = BN / 32;
    constexpr int NPA = (NPROD == 3) ? 2 : 1;
    constexpr int STAGE_A = 128 * 64 * NPA;
    constexpr int STAGE_B = BN * 64 * NPA;
    constexpr int STAGE = STAGE_A + STAGE_B;

    extern __shared__ char dynsm[];
    const uint32_t base0 = (smem_u32(dynsm) + 1023u) & ~1023u;

    const int tid = threadIdx.x;
    const int lane = tid & 31, wid = tid >> 5;
    const int wm = wid & 1, wn = wid >> 1;
    const int m0 = blockIdx.y * 128, n0 = blockIdx.x * BN;
    const int nch = K >> 5;

    float acc[4][NA][4];
#pragma unroll
    for (int i = 0; i < 4; i++)
#pragma unroll
        for (int j = 0; j < NA; j++)
#pragma unroll
            for (int q = 0; q < 4; q++) acc[i][j][q] = 0.f;

    auto fill = [&](int ci, int buf) {
        const int kb = ci * 64;
        const uint32_t st = base0 + buf * STAGE;
#pragma unroll
        for (int p = 0; p < NPA; p++) {
            const __half* Ap = p ? Alo : Ahi;
            const uint32_t dA = st + p * 8192;
#pragma unroll
            for (int i = 0; i < 2; i++) {
                int t2 = tid + i * 256;
                int r = t2 >> 2, c = t2 & 3;
                int row = m0 + r;
                int rowc = (row < M) ? row : (M - 1);
                const char* src = (const char*)(Ap + (size_t)rowc * K) + kb + c * 16;
                uint32_t ssize = (row < M) ? 16u : 0u;
                uint32_t dst = dA + (uint32_t)(r * 64 + ((c ^ ((r >> 1) & 3)) * 16));
                asm volatile("cp.async.cg.shared.global [%0], [%1], 16, %2;"
                             :: "r"(dst), "l"(src), "r"(ssize) : "memory");
            }
        }
#pragma unroll
        for (int p = 0; p < NPA; p++) {
            const __half* Wp = p ? Wlo : Whi;
            const uint32_t dB = st + STAGE_A + p * (BN * 64);
#pragma unroll
            for (int i = 0; i < BN / 64; i++) {
                int t2 = tid + i * 256;
                int r = t2 >> 2, c = t2 & 3;
                const char* src = (const char*)(Wp + (size_t)(n0 + r) * K) + kb + c * 16;
                uint32_t dst = dB + (uint32_t)(r * 64 + ((c ^ ((r >> 1) & 3)) * 16));
                asm volatile("cp.async.cg.shared.global [%0], [%1], 16;"
                             :: "r"(dst), "l"(src) : "memory");
            }
        }
        asm volatile("cp.async.commit_group;" ::: "memory");
    };

    auto compute = [&](int buf) {
        const uint32_t st = base0 + buf * STAGE;
        const uint32_t aHiB = st, aLoB = st + 8192;
        const uint32_t bHiB = st + STAGE_A, bLoB = st + STAGE_A + BN * 64;
#pragma unroll
        for (int ks = 0; ks < 2; ks++) {
            uint32_t ah[4][4], al[4][4];
#pragma unroll
            for (int ma = 0; ma < 4; ma++) {
                int r = wm * 64 + ma * 16 + (lane & 15);
                int c = ks * 2 + (lane >> 4);
                uint32_t off = (uint32_t)(r * 64 + ((c ^ ((r >> 1) & 3)) * 16));
                asm volatile("ldmatrix.sync.aligned.m8n8.x4.shared.b16 {%0,%1,%2,%3}, [%4];"
                             : "=r"(ah[ma][0]), "=r"(ah[ma][1]), "=r"(ah[ma][2]), "=r"(ah[ma][3])
                             : "r"(aHiB + off));
                if (NPROD == 3)
                    asm volatile("ldmatrix.sync.aligned.m8n8.x4.shared.b16 {%0,%1,%2,%3}, [%4];"
                                 : "=r"(al[ma][0]), "=r"(al[ma][1]), "=r"(al[ma][2]), "=r"(al[ma][3])
                                 : "r"(aLoB + off));
            }
#pragma unroll
            for (int nb = 0; nb < NA / 2; nb++) {
                int r = wn * (BN / 4) + nb * 16 + (lane & 7) + ((lane >> 4) & 1) * 8;
                int c = ks * 2 + ((lane >> 3) & 1);
                uint32_t off = (uint32_t)(r * 64 + ((c ^ ((r >> 1) & 3)) * 16));
                uint32_t b0, b1, b2, b3;
                asm volatile("ldmatrix.sync.aligned.m8n8.x4.shared.b16 {%0,%1,%2,%3}, [%4];"
                             : "=r"(b0), "=r"(b1), "=r"(b2), "=r"(b3) : "r"(bHiB + off));
#pragma unroll
                for (int ma = 0; ma < 4; ma++) {
                    MMA_F16(acc[ma][nb * 2], ah[ma], b0, b1);
                    MMA_F16(acc[ma][nb * 2 + 1], ah[ma], b2, b3);
                    if (NPROD == 3) {
                        MMA_F16(acc[ma][nb * 2], al[ma], b0, b1);
                        MMA_F16(acc[ma][nb * 2 + 1], al[ma], b2, b3);
                    }
                }
                if (NPROD == 3) {
                    asm volatile("ldmatrix.sync.aligned.m8n8.x4.shared.b16 {%0,%1,%2,%3}, [%4];"
                                 : "=r"(b0), "=r"(b1), "=r"(b2), "=r"(b3) : "r"(bLoB + off));
#pragma unroll
                    for (int ma = 0; ma < 4; ma++) {
                        MMA_F16(acc[ma][nb * 2], ah[ma], b0, b1);
                        MMA_F16(acc[ma][nb * 2 + 1], ah[ma], b2, b3);
                    }
                }
            }
        }
    };

    fill(0, 0);
    fill(1, 1);
    for (int ci = 0; ci < nch; ci++) {
        if (ci + 1 < nch) {
            asm volatile("cp.async.wait_group 1;" ::: "memory");
        } else {
            asm volatile("cp.async.wait_group 0;" ::: "memory");
        }
        __syncthreads();
        if (ci + 2 < nch) fill(ci + 2, (ci + 2) % 3);
        compute(ci % 3);
    }

    // ---- epilogue ----
#pragma unroll
    for (int ma = 0; ma < 4; ma++) {
        int r0 = m0 + wm * 64 + ma * 16 + (lane >> 2);
        float p0[4] = {0.f, 0.f, 0.f, 0.f}, p1[4] = {0.f, 0.f, 0.f, 0.f};
#pragma unroll
        for (int na = 0; na < NA; na++) {
            int c = n0 + wn * (BN / 4) + na * 8 + (lane & 3) * 2;
            float b0v = __ldg(bias + c), b1v = __ldg(bias + c + 1);
            float v00 = acc[ma][na][0] + b0v, v01 = acc[ma][na][1] + b1v;
            float v10 = acc[ma][na][2] + b0v, v11 = acc[ma][na][3] + b1v;
            if (relu) {
                v00 = fmaxf(v00, 0.f); v01 = fmaxf(v01, 0.f);
                v10 = fmaxf(v10, 0.f); v11 = fmaxf(v11, 0.f);
            }
            if (OUTMODE == 0) {
#pragma unroll
                for (int rr = 0; rr < 2; rr++) {
                    int row = r0 + rr * 8;
                    if (row >= M) continue;
                    float va = rr ? v10 : v00, vb = rr ? v11 : v01;
                    uint32_t hp = (uint32_t)__half_as_ushort(__float2half_rn(va)) |
                                  ((uint32_t)__half_as_ushort(__float2half_rn(vb)) << 16);
                    *(uint32_t*)(outH + (size_t)row * N + c) = hp;
                }
            } else {
                float4 w0 = __ldg((const float4*)(lw3 + c * 4));
                float4 w1 = __ldg((const float4*)(lw3 + (c + 1) * 4));
                p0[0] += v00 * w0.x + v01 * w1.x;  p0[1] += v00 * w0.y + v01 * w1.y;
                p0[2] += v00 * w0.z + v01 * w1.z;  p0[3] += v00 * w0.w + v01 * w1.w;
                p1[0] += v10 * w0.x + v11 * w1.x;  p1[1] += v10 * w0.y + v11 * w1.y;
                p1[2] += v10 * w0.z + v11 * w1.z;  p1[3] += v10 * w0.w + v11 * w1.w;
            }
        }
        if (OUTMODE == 1) {
#pragma unroll
            for (int j = 0; j < 4; j++) {
                p0[j] += __shfl_down_sync(0xffffffffu, p0[j], 2);
                p0[j] += __shfl_down_sync(0xffffffffu, p0[j], 1);
                p1[j] += __shfl_down_sync(0xffffffffu, p1[j], 2);
                p1[j] += __shfl_down_sync(0xffffffffu, p1[j], 1);
            }
            if ((lane & 3) == 0) {
                if (r0 < M) {
#pragma unroll
                    for (int j = 0; j < 4; j++) atomicAdd(&nsum[(size_t)r0 * 4 + j], p0[j]);
                }
                if (r0 + 8 < M) {
#pragma unroll
                    for (int j = 0; j < 4; j++) atomicAdd(&nsum[(size_t)(r0 + 8) * 4 + j], p1[j]);
                }
            }
        }
    }
}

// ================= pooling (warp-aggregated) =================
__global__ void pool_kernel(const int* __restrict__ batch) {
    int i = blockIdx.x * 256 + threadIdx.x;
    int lane = threadIdx.x & 31;
    bool valid = i < NN;
    int g = valid ? batch[i] : -1;
    float4 v = valid ? *(const float4*)(g_nsum + (size_t)i * 4)
                     : make_float4(0.f, 0.f, 0.f, 0.f);
    int g0 = __shfl_sync(0xffffffffu, g, 0);
    bool uni = __all_sync(0xffffffffu, valid && g == g0);
    if (uni) {
#pragma unroll
        for (int o = 16; o > 0; o >>= 1) {
            v.x += __shfl_down_sync(0xffffffffu, v.x, o);
            v.y += __shfl_down_sync(0xffffffffu, v.y, o);
            v.z += __shfl_down_sync(0xffffffffu, v.z, o);
            v.w += __shfl_down_sync(0xffffffffu, v.w, o);
        }
        if (lane == 0) {
            atomicAdd(&g_gsum[g0 * 4 + 0], v.x);
            atomicAdd(&g_gsum[g0 * 4 + 1], v.y);
            atomicAdd(&g_gsum[g0 * 4 + 2], v.z);
            atomicAdd(&g_gsum[g0 * 4 + 3], v.w);
            atomicAdd(&g_gcnt[g0], 32);
        }
    } else if (valid) {
        atomicAdd(&g_gsum[g * 4 + 0], v.x);
        atomicAdd(&g_gsum[g * 4 + 1], v.y);
        atomicAdd(&g_gsum[g * 4 + 2], v.z);
        atomicAdd(&g_gsum[g * 4 + 3], v.w);
        atomicAdd(&g_gcnt[g], 1);
    }
}

__global__ void finalize_kernel(float* __restrict__ out, const float* __restrict__ lb3) {
    int i = blockIdx.x * blockDim.x + threadIdx.x;
    if (i < NG * 4) {
        int cnt = g_gcnt[i >> 2];
        out[i] = (cnt > 0) ? (g_gsum[i] / (float)cnt + lb3[i & 3]) : 0.f;
    }
}

// ================= launch =================
extern "C" void kernel_launch(void* const* d_in, const int* in_sizes, int n_in,
                              void* d_out, int out_size) {
    const float* x    = (const float*)d_in[0];
    const int*   ei   = (const int*)d_in[1];
    const int*   bat  = (const int*)d_in[2];
    const float* W1   = (const float*)d_in[3];
    const float* b1   = (const float*)d_in[4];
    const float* W2   = (const float*)d_in[5];
    const float* b2   = (const float*)d_in[6];
    const float* W3   = (const float*)d_in[7];
    const float* b3   = (const float*)d_in[8];
    const float* lw1  = (const float*)d_in[9];
    const float* lb1  = (const float*)d_in[10];
    const float* lw2  = (const float*)d_in[11];
    const float* lb2  = (const float*)d_in[12];
    const float* lw3  = (const float*)d_in[13];
    const float* lb3  = (const float*)d_in[14];
    float* out = (float*)d_out;

    const int* src = ei;
    const int* dst = ei + NE;

    float* nsum;
    cudaGetSymbolAddress((void**)&nsum, g_nsum);
    __half *Ahi, *Alo, *act1, *act2, *Whi, *Wlo;
    cudaGetSymbolAddress((void**)&Ahi, g_Ahi);
    cudaGetSymbolAddress((void**)&Alo, g_Alo);
    cudaGetSymbolAddress((void**)&act1, g_act1);
    cudaGetSymbolAddress((void**)&act2, g_act2);
    cudaGetSymbolAddress((void**)&Whi, g_Whi);
    cudaGetSymbolAddress((void**)&Wlo, g_Wlo);

    constexpr int SM_128_3 = 3 * (2 * 8192 + 128 * 64 * 2) + 1024;  //  99328
    constexpr int SM_256_3 = 3 * (2 * 8192 + 256 * 64 * 2) + 1024;  // 148480
    constexpr int SM_256_1 = 3 * (8192 + 256 * 64) + 1024;          //  74752
    cudaFuncSetAttribute(gemm_mma<128, 3, 0>, cudaFuncAttributeMaxDynamicSharedMemorySize, SM_128_3);
    cudaFuncSetAttribute(gemm_mma<256, 3, 0>, cudaFuncAttributeMaxDynamicSharedMemorySize, SM_256_3);
    cudaFuncSetAttribute(gemm_mma<256, 1, 0>, cudaFuncAttributeMaxDynamicSharedMemorySize, SM_256_1);
    cudaFuncSetAttribute(gemm_mma<256, 1, 1>, cudaFuncAttributeMaxDynamicSharedMemorySize, SM_256_1);

    // ---- graph preprocessing ----
    zero_kernel<<<(NN * 4 + 255) / 256, 256>>>();
    hist_kernel<<<(NE + 255) / 256, 256>>>(dst);
    invsqrt_kernel<<<(NN + 255) / 256, 256>>>();
    scan1_kernel<<<NBLK, 256>>>();
    scan2_kernel<<<1, 512>>>();
    scan3_kernel<<<NBLK, 256>>>();
    csr_fill_kernel<<<(NE + 255) / 256, 256>>>(src, dst);

    const int aggBlocks = (NN + 3) / 4;
    const int tilesM = (NN + 127) / 128;   // 782

    // ---- layer 1: x->fp16, agg, 3-term mma (K=128, N=128), fp16 out ----
    xconv_kernel<<<(int)(((size_t)NN * 128 + 255) / 256), 256>>>(x, act1, (size_t)NN * 128);
    agg16_kernel<128><<<aggBlocks, 128>>>(act1, Ahi, Alo);
    wconv_kernel<<<(128 * 128 + 255) / 256, 256>>>(W1, 128, 128, 1);
    gemm_mma<128, 3, 0><<<dim3(1, tilesM), 256, SM_128_3>>>(
        Ahi, Alo, Whi, Wlo, b1, NN, 128, 128, 1, act1, nullptr, nullptr);

    // ---- layer 2 (K=128, N=256) ----
    agg16_kernel<128><<<aggBlocks, 128>>>(act1, Ahi, Alo);
    wconv_kernel<<<(256 * 128 + 255) / 256, 256>>>(W2, 128, 256, 1);
    gemm_mma<256, 3, 0><<<dim3(1, tilesM), 256, SM_256_3>>>(
        Ahi, Alo, Whi, Wlo, b2, NN, 128, 256, 1, act1, nullptr, nullptr);

    // ---- layer 3 (K=256, N=512), fp16 out ----
    agg16_kernel<256><<<aggBlocks, 128>>>(act1, Ahi, Alo);
    wconv_kernel<<<(512 * 256 + 255) / 256, 256>>>(W3, 256, 512, 1);
    gemm_mma<256, 3, 0><<<dim3(2, tilesM), 256, SM_256_3>>>(
        Ahi, Alo, Whi, Wlo, b3, NN, 256, 512, 0, act1, nullptr, nullptr);

    // ---- MLP1 (K=512, N=1024), pure fp16, fp16 out ----
    wconv_kernel<<<(1024 * 512 + 255) / 256, 256>>>(lw1, 512, 1024, 0);
    gemm_mma<256, 1, 0><<<dim3(4, tilesM), 256, SM_256_1>>>(
        act1, nullptr, Whi, nullptr, lb1, NN, 512, 1024, 1, act2, nullptr, nullptr);

    // ---- MLP2 (K=1024, N=512), pure fp16, fused 512->4 + node-sum ----
    wconv_kernel<<<(512 * 1024 + 255) / 256, 256>>>(lw2, 1024, 512, 0);
    gemm_mma<256, 1, 1><<<dim3(2, tilesM), 256, SM_256_1>>>(
        act2, nullptr, Whi, nullptr, lb2, NN, 1024, 512, 1, nullptr, lw3, nsum);

    // ---- pooling ----
    pool_kernel<<<NBLK, 256>>>(bat);
    finalize_kernel<<<(NG * 4 + 255) / 256, 256>>>(out, lb3);
}

// round 10
// speedup vs baseline: 4.9445x; 1.0081x over previous
#include <cuda_runtime.h>
#include <cuda_fp16.h>
#include <cstdint>

#define NN 100000
#define NE 3200000
#define NG 256
#define NBLK 391   // ceil(NN/256)

// ---- weight plane offsets (elements) ----
#define OFF_W1  0          // 128x128  = 16384
#define OFF_W2  16384      // 256x128  = 32768
#define OFF_W3  49152      // 512x256  = 131072
#define OFF_L1  180224     // 1024x512 = 524288
#define OFF_L2  704512     // 512x1024 = 524288  -> end 1228800

// ================= device scratch (no allocations allowed) =================
__device__ int   g_cnt[NN];
__device__ int   g_rowptr[NN + 1];
__device__ int   g_cursor[NN];
__device__ int   g_bsum[NBLK];
__device__ int2  g_edge[NE];                  // (src, wgt bits) packed
__device__ float g_is[NN];
__device__ __half g_Ahi[(size_t)NN * 256];
__device__ __half g_Alo[(size_t)NN * 256];
__device__ __half g_act1[(size_t)NN * 1024];
__device__ __half g_act2[(size_t)NN * 1024];
__device__ __half g_Whi[1 << 21];
__device__ __half g_Wlo[1 << 15];             // only L1 needs a lo plane
__device__ float g_nsum[(size_t)NN * 4];
__device__ float g_gsum[NG * 4];
__device__ int   g_gcnt[NG];

__device__ __forceinline__ uint32_t smem_u32(const void* p) {
    uint32_t a;
    asm("{ .reg .u64 t; cvta.to.shared.u64 t, %1; cvt.u32.u64 %0, t; }" : "=r"(a) : "l"(p));
    return a;
}

// ================= graph preprocessing =================
__global__ void zero_kernel() {
    int i = blockIdx.x * blockDim.x + threadIdx.x;
    if (i < NN) g_cnt[i] = 0;
    if (i < NN * 4) g_nsum[i] = 0.f;
    if (i < NG * 4) g_gsum[i] = 0.f;
    if (i < NG) g_gcnt[i] = 0;
}

__global__ void hist_kernel(const int* __restrict__ dst) {
    int e = blockIdx.x * blockDim.x + threadIdx.x;
    if (e < NE) atomicAdd(&g_cnt[dst[e]], 1);
}

__global__ void invsqrt_kernel() {
    int i = blockIdx.x * blockDim.x + threadIdx.x;
    if (i < NN) g_is[i] = rsqrtf((float)(g_cnt[i] + 1));
}

__global__ void scan1_kernel() {
    int i = blockIdx.x * 256 + threadIdx.x;
    int v = (i < NN) ? g_cnt[i] : 0;
#pragma unroll
    for (int o = 16; o > 0; o >>= 1) v += __shfl_down_sync(0xffffffffu, v, o);
    __shared__ int ws[8];
    if ((threadIdx.x & 31) == 0) ws[threadIdx.x >> 5] = v;
    __syncthreads();
    if (threadIdx.x < 8) {
        int s = ws[threadIdx.x];
#pragma unroll
        for (int o = 4; o > 0; o >>= 1) s += __shfl_down_sync(0xffu, s, o);
        if (threadIdx.x == 0) g_bsum[blockIdx.x] = s;
    }
}

__global__ void scan2_kernel() {
    int tid = threadIdx.x;
    int v = (tid < NBLK) ? g_bsum[tid] : 0;
    __shared__ int sm[512];
    sm[tid] = v;
    __syncthreads();
    for (int o = 1; o < 512; o <<= 1) {
        int a = (tid >= o) ? sm[tid - o] : 0;
        __syncthreads();
        sm[tid] += a;
        __syncthreads();
    }
    if (tid < NBLK) g_bsum[tid] = sm[tid] - v;
    if (tid == NBLK - 1) g_rowptr[NN] = sm[tid];
}

__global__ void scan3_kernel() {
    int i = blockIdx.x * 256 + threadIdx.x;
    int v = (i < NN) ? g_cnt[i] : 0;
    int lane = threadIdx.x & 31, w = threadIdx.x >> 5;
    int x = v;
#pragma unroll
    for (int o = 1; o < 32; o <<= 1) {
        int t = __shfl_up_sync(0xffffffffu, x, o);
        if (lane >= o) x += t;
    }
    __shared__ int ws[8];
    if (lane == 31) ws[w] = x;
    __syncthreads();
    if (threadIdx.x < 8) {
        int s = ws[threadIdx.x];
#pragma unroll
        for (int o = 1; o < 8; o <<= 1) {
            int t = __shfl_up_sync(0xffu, s, o);
            if ((int)threadIdx.x >= o) s += t;
        }
        ws[threadIdx.x] = s;
    }
    __syncthreads();
    int excl = x - v + (w ? ws[w - 1] : 0) + g_bsum[blockIdx.x];
    if (i < NN) {
        g_rowptr[i] = excl;
        g_cursor[i] = excl;
    }
}

__global__ void csr_fill_kernel(const int* __restrict__ src, const int* __restrict__ dst) {
    int e = blockIdx.x * blockDim.x + threadIdx.x;
    if (e >= NE) return;
    int d = dst[e];
    int s = src[e];
    int p = atomicAdd(&g_cursor[d], 1);
    g_edge[p] = make_int2(s, __float_as_int(g_is[s] * g_is[d]));
}

// ================= fp32 x -> fp16 plane =================
__global__ void xconv_kernel(const float* __restrict__ x, __half* __restrict__ o, size_t total) {
    size_t i = blockIdx.x * (size_t)blockDim.x + threadIdx.x;
    if (i < total) o[i] = __float2half_rn(x[i]);
}

// ================= aggregation: fp16 gather, fp32 accum, hi/lo split out =====
template <int H>
__global__ void agg16_kernel(const __half* __restrict__ h,
                             __half* __restrict__ outHi, __half* __restrict__ outLo) {
    const int node = blockIdx.x * 4 + (threadIdx.x >> 5);
    if (node >= NN) return;
    const int lane = threadIdx.x & 31;
    constexpr int U = H / 128;

    float acc[U][4];
    float self = g_is[node];
    self = self * self;
    const uint2* hrow = (const uint2*)(h + (size_t)node * H);
#pragma unroll
    for (int u = 0; u < U; u++) {
        uint2 t = hrow[lane + 32 * u];
        float2 a = __half22float2(*(const __half2*)&t.x);
        float2 b = __half22float2(*(const __half2*)&t.y);
        acc[u][0] = self * a.x; acc[u][1] = self * a.y;
        acc[u][2] = self * b.x; acc[u][3] = self * b.y;
    }
    const int beg = g_rowptr[node];
    const int end = g_rowptr[node + 1];
    int p = beg;
    for (; p + 2 <= end; p += 2) {
        int2 e0 = g_edge[p], e1 = g_edge[p + 1];
        float w0 = __int_as_float(e0.y), w1 = __int_as_float(e1.y);
        const uint2* s0 = (const uint2*)(h + (size_t)e0.x * H);
        const uint2* s1 = (const uint2*)(h + (size_t)e1.x * H);
#pragma unroll
        for (int u = 0; u < U; u++) {
            uint2 t0 = s0[lane + 32 * u];
            uint2 t1 = s1[lane + 32 * u];
            float2 a0 = __half22float2(*(const __half2*)&t0.x);
            float2 b0 = __half22float2(*(const __half2*)&t0.y);
            float2 a1 = __half22float2(*(const __half2*)&t1.x);
            float2 b1 = __half22float2(*(const __half2*)&t1.y);
            acc[u][0] += w0 * a0.x + w1 * a1.x;
            acc[u][1] += w0 * a0.y + w1 * a1.y;
            acc[u][2] += w0 * b0.x + w1 * b1.x;
            acc[u][3] += w0 * b0.y + w1 * b1.y;
        }
    }
    if (p < end) {
        int2 e0 = g_edge[p];
        float w0 = __int_as_float(e0.y);
        const uint2* s0 = (const uint2*)(h + (size_t)e0.x * H);
#pragma unroll
        for (int u = 0; u < U; u++) {
            uint2 t0 = s0[lane + 32 * u];
            float2 a0 = __half22float2(*(const __half2*)&t0.x);
            float2 b0 = __half22float2(*(const __half2*)&t0.y);
            acc[u][0] += w0 * a0.x; acc[u][1] += w0 * a0.y;
            acc[u][2] += w0 * b0.x; acc[u][3] += w0 * b0.y;
        }
    }
#pragma unroll
    for (int u = 0; u < U; u++) {
        ushort hs[4], ls[4];
#pragma unroll
        for (int q = 0; q < 4; q++) {
            __half hh = __float2half_rn(acc[u][q]);
            hs[q] = __half_as_ushort(hh);
            ls[q] = __half_as_ushort(__float2half_rn(acc[u][q] - __half2float(hh)));
        }
        uint2 ph = make_uint2((uint32_t)hs[0] | ((uint32_t)hs[1] << 16),
                              (uint32_t)hs[2] | ((uint32_t)hs[3] << 16));
        uint2 pl = make_uint2((uint32_t)ls[0] | ((uint32_t)ls[1] << 16),
                              (uint32_t)ls[2] | ((uint32_t)ls[3] << 16));
        ((uint2*)(outHi + (size_t)node * H))[lane + 32 * u] = ph;
        ((uint2*)(outLo + (size_t)node * H))[lane + 32 * u] = pl;
    }
}

// ================= fp32 -> fp16 weight conversion (transposed, offset) =======
__global__ void wconv_kernel(const float* __restrict__ W, int K, int N, int off, int both) {
    int idx = blockIdx.x * blockDim.x + threadIdx.x;
    if (idx >= N * K) return;
    int n = idx / K, k = idx - n * K;
    float v = W[(size_t)k * N + n];
    __half hi = __float2half_rn(v);
    g_Whi[off + idx] = hi;
    if (both) g_Wlo[idx] = __float2half_rn(v - __half2float(hi));
}

// ================= tensor-core GEMM (fp16, mma.sync) =========================
#define MMA_F16(ACC, AF, B0, B1)                                                 \
    asm volatile(                                                                \
        "mma.sync.aligned.m16n8k16.row.col.f32.f16.f16.f32 "                     \
        "{%0,%1,%2,%3}, {%4,%5,%6,%7}, {%8,%9}, {%0,%1,%2,%3};"                  \
        : "+f"((ACC)[0]), "+f"((ACC)[1]), "+f"((ACC)[2]), "+f"((ACC)[3])         \
        : "r"((AF)[0]), "r"((AF)[1]), "r"((AF)[2]), "r"((AF)[3]),                \
          "r"(B0), "r"(B1))

// NPROD 3: AhiWhi+AloWhi+AhiWlo. NPROD 2: (Ahi+Alo)Whi. NPROD 1: Ahi*Whi.
// OUTMODE 0: fp16 plane out. OUTMODE 1: fused 512->4 dot + node-sum.
template <int BN, int NPROD, int OUTMODE>
__global__ __launch_bounds__(256) void gemm_mma(
    const __half* __restrict__ Ahi, const __half* __restrict__ Alo,
    const __half* __restrict__ Whi, const __half* __restrict__ Wlo,
    const float* __restrict__ bias, int M, int K, int N, int relu,
    __half* __restrict__ outH,
    const float* __restrict__ lw3, float* __restrict__ nsum) {
    constexpr int NA = BN / 32;
    constexpr int NPA_A = (NPROD >= 2) ? 2 : 1;
    constexpr int NPA_B = (NPROD == 3) ? 2 : 1;
    constexpr int STAGE_A = 128 * 64 * NPA_A;
    constexpr int STAGE_B = BN * 64 * NPA_B;
    constexpr int STAGE = STAGE_A + STAGE_B;

    extern __shared__ char dynsm[];
    const uint32_t base0 = (smem_u32(dynsm) + 1023u) & ~1023u;

    const int tid = threadIdx.x;
    const int lane = tid & 31, wid = tid >> 5;
    const int wm = wid & 1, wn = wid >> 1;
    const int m0 = blockIdx.y * 128, n0 = blockIdx.x * BN;
    const int nch = K >> 5;

    float acc[4][NA][4];
#pragma unroll
    for (int i = 0; i < 4; i++)
#pragma unroll
        for (int j = 0; j < NA; j++)
#pragma unroll
            for (int q = 0; q < 4; q++) acc[i][j][q] = 0.f;

    auto fill = [&](int ci, int buf) {
        const int kb = ci * 64;
        const uint32_t st = base0 + buf * STAGE;
#pragma unroll
        for (int p = 0; p < NPA_A; p++) {
            const __half* Ap = p ? Alo : Ahi;
            const uint32_t dA = st + p * 8192;
#pragma unroll
            for (int i = 0; i < 2; i++) {
                int t2 = tid + i * 256;
                int r = t2 >> 2, c = t2 & 3;
                int row = m0 + r;
                int rowc = (row < M) ? row : (M - 1);
                const char* src = (const char*)(Ap + (size_t)rowc * K) + kb + c * 16;
                uint32_t ssize = (row < M) ? 16u : 0u;
                uint32_t dst = dA + (uint32_t)(r * 64 + ((c ^ ((r >> 1) & 3)) * 16));
                asm volatile("cp.async.cg.shared.global [%0], [%1], 16, %2;"
                             :: "r"(dst), "l"(src), "r"(ssize) : "memory");
            }
        }
#pragma unroll
        for (int p = 0; p < NPA_B; p++) {
            const __half* Wp = p ? Wlo : Whi;
            const uint32_t dB = st + STAGE_A + p * (BN * 64);
#pragma unroll
            for (int i = 0; i < BN / 64; i++) {
                int t2 = tid + i * 256;
                int r = t2 >> 2, c = t2 & 3;
                const char* src = (const char*)(Wp + (size_t)(n0 + r) * K) + kb + c * 16;
                uint32_t dst = dB + (uint32_t)(r * 64 + ((c ^ ((r >> 1) & 3)) * 16));
                asm volatile("cp.async.cg.shared.global [%0], [%1], 16;"
                             :: "r"(dst), "l"(src) : "memory");
            }
        }
        asm volatile("cp.async.commit_group;" ::: "memory");
    };

    auto compute = [&](int buf) {
        const uint32_t st = base0 + buf * STAGE;
        const uint32_t aHiB = st, aLoB = st + 8192;
        const uint32_t bHiB = st + STAGE_A, bLoB = st + STAGE_A + BN * 64;
#pragma unroll
        for (int ks = 0; ks < 2; ks++) {
            uint32_t ah[4][4], al[4][4];
#pragma unroll
            for (int ma = 0; ma < 4; ma++) {
                int r = wm * 64 + ma * 16 + (lane & 15);
                int c = ks * 2 + (lane >> 4);
                uint32_t off = (uint32_t)(r * 64 + ((c ^ ((r >> 1) & 3)) * 16));
                asm volatile("ldmatrix.sync.aligned.m8n8.x4.shared.b16 {%0,%1,%2,%3}, [%4];"
                             : "=r"(ah[ma][0]), "=r"(ah[ma][1]), "=r"(ah[ma][2]), "=r"(ah[ma][3])
                             : "r"(aHiB + off));
                if (NPROD >= 2)
                    asm volatile("ldmatrix.sync.aligned.m8n8.x4.shared.b16 {%0,%1,%2,%3}, [%4];"
                                 : "=r"(al[ma][0]), "=r"(al[ma][1]), "=r"(al[ma][2]), "=r"(al[ma][3])
                                 : "r"(aLoB + off));
            }
#pragma unroll
            for (int nb = 0; nb < NA / 2; nb++) {
                int r = wn * (BN / 4) + nb * 16 + (lane & 7) + ((lane >> 4) & 1) * 8;
                int c = ks * 2 + ((lane >> 3) & 1);
                uint32_t off = (uint32_t)(r * 64 + ((c ^ ((r >> 1) & 3)) * 16));
                uint32_t b0, b1, b2, b3;
                asm volatile("ldmatrix.sync.aligned.m8n8.x4.shared.b16 {%0,%1,%2,%3}, [%4];"
                             : "=r"(b0), "=r"(b1), "=r"(b2), "=r"(b3) : "r"(bHiB + off));
#pragma unroll
                for (int ma = 0; ma < 4; ma++) {
                    MMA_F16(acc[ma][nb * 2], ah[ma], b0, b1);
                    MMA_F16(acc[ma][nb * 2 + 1], ah[ma], b2, b3);
                    if (NPROD >= 2) {
                        MMA_F16(acc[ma][nb * 2], al[ma], b0, b1);
                        MMA_F16(acc[ma][nb * 2 + 1], al[ma], b2, b3);
                    }
                }
                if (NPROD == 3) {
                    asm volatile("ldmatrix.sync.aligned.m8n8.x4.shared.b16 {%0,%1,%2,%3}, [%4];"
                                 : "=r"(b0), "=r"(b1), "=r"(b2), "=r"(b3) : "r"(bLoB + off));
#pragma unroll
                    for (int ma = 0; ma < 4; ma++) {
                        MMA_F16(acc[ma][nb * 2], ah[ma], b0, b1);
                        MMA_F16(acc[ma][nb * 2 + 1], ah[ma], b2, b3);
                    }
                }
            }
        }
    };

    fill(0, 0);
    fill(1, 1);
    for (int ci = 0; ci < nch; ci++) {
        if (ci + 1 < nch) {
            asm volatile("cp.async.wait_group 1;" ::: "memory");
        } else {
            asm volatile("cp.async.wait_group 0;" ::: "memory");
        }
        __syncthreads();
        if (ci + 2 < nch) fill(ci + 2, (ci + 2) % 3);
        compute(ci % 3);
    }

    // ---- epilogue ----
#pragma unroll
    for (int ma = 0; ma < 4; ma++) {
        int r0 = m0 + wm * 64 + ma * 16 + (lane >> 2);
        float p0[4] = {0.f, 0.f, 0.f, 0.f}, p1[4] = {0.f, 0.f, 0.f, 0.f};
#pragma unroll
        for (int na = 0; na < NA; na++) {
            int c = n0 + wn * (BN / 4) + na * 8 + (lane & 3) * 2;
            float b0v = __ldg(bias + c), b1v = __ldg(bias + c + 1);
            float v00 = acc[ma][na][0] + b0v, v01 = acc[ma][na][1] + b1v;
            float v10 = acc[ma][na][2] + b0v, v11 = acc[ma][na][3] + b1v;
            if (relu) {
                v00 = fmaxf(v00, 0.f); v01 = fmaxf(v01, 0.f);
                v10 = fmaxf(v10, 0.f); v11 = fmaxf(v11, 0.f);
            }
            if (OUTMODE == 0) {
#pragma unroll
                for (int rr = 0; rr < 2; rr++) {
                    int row = r0 + rr * 8;
                    if (row >= M) continue;
                    float va = rr ? v10 : v00, vb = rr ? v11 : v01;
                    uint32_t hp = (uint32_t)__half_as_ushort(__float2half_rn(va)) |
                                  ((uint32_t)__half_as_ushort(__float2half_rn(vb)) << 16);
                    *(uint32_t*)(outH + (size_t)row * N + c) = hp;
                }
            } else {
                float4 w0 = __ldg((const float4*)(lw3 + c * 4));
                float4 w1 = __ldg((const float4*)(lw3 + (c + 1) * 4));
                p0[0] += v00 * w0.x + v01 * w1.x;  p0[1] += v00 * w0.y + v01 * w1.y;
                p0[2] += v00 * w0.z + v01 * w1.z;  p0[3] += v00 * w0.w + v01 * w1.w;
                p1[0] += v10 * w0.x + v11 * w1.x;  p1[1] += v10 * w0.y + v11 * w1.y;
                p1[2] += v10 * w0.z + v11 * w1.z;  p1[3] += v10 * w0.w + v11 * w1.w;
            }
        }
        if (OUTMODE == 1) {
#pragma unroll
            for (int j = 0; j < 4; j++) {
                p0[j] += __shfl_down_sync(0xffffffffu, p0[j], 2);
                p0[j] += __shfl_down_sync(0xffffffffu, p0[j], 1);
                p1[j] += __shfl_down_sync(0xffffffffu, p1[j], 2);
                p1[j] += __shfl_down_sync(0xffffffffu, p1[j], 1);
            }
            if ((lane & 3) == 0) {
                if (r0 < M) {
#pragma unroll
                    for (int j = 0; j < 4; j++) atomicAdd(&nsum[(size_t)r0 * 4 + j], p0[j]);
                }
                if (r0 + 8 < M) {
#pragma unroll
                    for (int j = 0; j < 4; j++) atomicAdd(&nsum[(size_t)(r0 + 8) * 4 + j], p1[j]);
                }
            }
        }
    }
}

// ================= pooling (warp-aggregated) =================
__global__ void pool_kernel(const int* __restrict__ batch) {
    int i = blockIdx.x * 256 + threadIdx.x;
    int lane = threadIdx.x & 31;
    bool valid = i < NN;
    int g = valid ? batch[i] : -1;
    float4 v = valid ? *(const float4*)(g_nsum + (size_t)i * 4)
                     : make_float4(0.f, 0.f, 0.f, 0.f);
    int g0 = __shfl_sync(0xffffffffu, g, 0);
    bool uni = __all_sync(0xffffffffu, valid && g == g0);
    if (uni) {
#pragma unroll
        for (int o = 16; o > 0; o >>= 1) {
            v.x += __shfl_down_sync(0xffffffffu, v.x, o);
            v.y += __shfl_down_sync(0xffffffffu, v.y, o);
            v.z += __shfl_down_sync(0xffffffffu, v.z, o);
            v.w += __shfl_down_sync(0xffffffffu, v.w, o);
        }
        if (lane == 0) {
            atomicAdd(&g_gsum[g0 * 4 + 0], v.x);
            atomicAdd(&g_gsum[g0 * 4 + 1], v.y);
            atomicAdd(&g_gsum[g0 * 4 + 2], v.z);
            atomicAdd(&g_gsum[g0 * 4 + 3], v.w);
            atomicAdd(&g_gcnt[g0], 32);
        }
    } else if (valid) {
        atomicAdd(&g_gsum[g * 4 + 0], v.x);
        atomicAdd(&g_gsum[g * 4 + 1], v.y);
        atomicAdd(&g_gsum[g * 4 + 2], v.z);
        atomicAdd(&g_gsum[g * 4 + 3], v.w);
        atomicAdd(&g_gcnt[g], 1);
    }
}

__global__ void finalize_kernel(float* __restrict__ out, const float* __restrict__ lb3) {
    int i = blockIdx.x * blockDim.x + threadIdx.x;
    if (i < NG * 4) {
        int cnt = g_gcnt[i >> 2];
        out[i] = (cnt > 0) ? (g_gsum[i] / (float)cnt + lb3[i & 3]) : 0.f;
    }
}

// ================= launch =================
extern "C" void kernel_launch(void* const* d_in, const int* in_sizes, int n_in,
                              void* d_out, int out_size) {
    const float* x    = (const float*)d_in[0];
    const int*   ei   = (const int*)d_in[1];
    const int*   bat  = (const int*)d_in[2];
    const float* W1   = (const float*)d_in[3];
    const float* b1   = (const float*)d_in[4];
    const float* W2   = (const float*)d_in[5];
    const float* b2   = (const float*)d_in[6];
    const float* W3   = (const float*)d_in[7];
    const float* b3   = (const float*)d_in[8];
    const float* lw1  = (const float*)d_in[9];
    const float* lb1  = (const float*)d_in[10];
    const float* lw2  = (const float*)d_in[11];
    const float* lb2  = (const float*)d_in[12];
    const float* lw3  = (const float*)d_in[13];
    const float* lb3  = (const float*)d_in[14];
    float* out = (float*)d_out;

    const int* src = ei;
    const int* dst = ei + NE;

    float* nsum;
    cudaGetSymbolAddress((void**)&nsum, g_nsum);
    __half *Ahi, *Alo, *act1, *act2, *Whi, *Wlo;
    cudaGetSymbolAddress((void**)&Ahi, g_Ahi);
    cudaGetSymbolAddress((void**)&Alo, g_Alo);
    cudaGetSymbolAddress((void**)&act1, g_act1);
    cudaGetSymbolAddress((void**)&act2, g_act2);
    cudaGetSymbolAddress((void**)&Whi, g_Whi);
    cudaGetSymbolAddress((void**)&Wlo, g_Wlo);

    constexpr int SM_128_3 = 3 * (2 * 8192 + 128 * 64 * 2) + 1024;  // 99328
    constexpr int SM_256_2 = 3 * (2 * 8192 + 256 * 64) + 1024;      // 99328
    constexpr int SM_256_1 = 3 * (8192 + 256 * 64) + 1024;          // 74752
    cudaFuncSetAttribute(gemm_mma<128, 3, 0>, cudaFuncAttributeMaxDynamicSharedMemorySize, SM_128_3);
    cudaFuncSetAttribute(gemm_mma<256, 2, 0>, cudaFuncAttributeMaxDynamicSharedMemorySize, SM_256_2);
    cudaFuncSetAttribute(gemm_mma<256, 1, 0>, cudaFuncAttributeMaxDynamicSharedMemorySize, SM_256_1);
    cudaFuncSetAttribute(gemm_mma<256, 1, 1>, cudaFuncAttributeMaxDynamicSharedMemorySize, SM_256_1);

    // ---- all weight conversions upfront (independent of graph work) ----
    wconv_kernel<<<(128 * 128 + 255) / 256, 256>>>(W1, 128, 128, OFF_W1, 1);
    wconv_kernel<<<(256 * 128 + 255) / 256, 256>>>(W2, 128, 256, OFF_W2, 0);
    wconv_kernel<<<(512 * 256 + 255) / 256, 256>>>(W3, 256, 512, OFF_W3, 0);
    wconv_kernel<<<(1024 * 512 + 255) / 256, 256>>>(lw1, 512, 1024, OFF_L1, 0);
    wconv_kernel<<<(512 * 1024 + 255) / 256, 256>>>(lw2, 1024, 512, OFF_L2, 0);
    xconv_kernel<<<(int)(((size_t)NN * 128 + 255) / 256), 256>>>(x, act1, (size_t)NN * 128);

    // ---- graph preprocessing ----
    zero_kernel<<<(NN * 4 + 255) / 256, 256>>>();
    hist_kernel<<<(NE + 255) / 256, 256>>>(dst);
    invsqrt_kernel<<<(NN + 255) / 256, 256>>>();
    scan1_kernel<<<NBLK, 256>>>();
    scan2_kernel<<<1, 512>>>();
    scan3_kernel<<<NBLK, 256>>>();
    csr_fill_kernel<<<(NE + 255) / 256, 256>>>(src, dst);

    const int aggBlocks = (NN + 3) / 4;
    const int tilesM = (NN + 127) / 128;   // 782

    // ---- layer 1: agg, 3-term mma (K=128, N=128) ----
    agg16_kernel<128><<<aggBlocks, 128>>>(act1, Ahi, Alo);
    gemm_mma<128, 3, 0><<<dim3(1, tilesM), 256, SM_128_3>>>(
        Ahi, Alo, Whi + OFF_W1, Wlo, b1, NN, 128, 128, 1, act1, nullptr, nullptr);

    // ---- layer 2: 2-term (K=128, N=256) ----
    agg16_kernel<128><<<aggBlocks, 128>>>(act1, Ahi, Alo);
    gemm_mma<256, 2, 0><<<dim3(1, tilesM), 256, SM_256_2>>>(
        Ahi, Alo, Whi + OFF_W2, nullptr, b2, NN, 128, 256, 1, act1, nullptr, nullptr);

    // ---- layer 3: 2-term (K=256, N=512) ----
    agg16_kernel<256><<<aggBlocks, 128>>>(act1, Ahi, Alo);
    gemm_mma<256, 2, 0><<<dim3(2, tilesM), 256, SM_256_2>>>(
        Ahi, Alo, Whi + OFF_W3, nullptr, b3, NN, 256, 512, 0, act1, nullptr, nullptr);

    // ---- MLP1: pure fp16 (K=512, N=1024) ----
    gemm_mma<256, 1, 0><<<dim3(4, tilesM), 256, SM_256_1>>>(
        act1, nullptr, Whi + OFF_L1, nullptr, lb1, NN, 512, 1024, 1, act2, nullptr, nullptr);

    // ---- MLP2: pure fp16 (K=1024, N=512), fused 512->4 + node-sum ----
    gemm_mma<256, 1, 1><<<dim3(2, tilesM), 256, SM_256_1>>>(
        act2, nullptr, Whi + OFF_L2, nullptr, lb2, NN, 1024, 512, 1, nullptr, lw3, nsum);

    // ---- pooling ----
    pool_kernel<<<NBLK, 256>>>(bat);
    finalize_kernel<<<(NG * 4 + 255) / 256, 256>>>(out, lb3);
}

// round 11
// speedup vs baseline: 5.2154x; 1.0548x over previous
#include <cuda_runtime.h>
#include <cuda_fp16.h>
#include <cstdint>

#define NN 100000
#define NE 3200000
#define NG 256
#define NBLK 391   // ceil(NN/256)

// ---- weight plane offsets (elements) ----
#define OFF_W1  0          // 128x128  = 16384
#define OFF_W2  16384      // 256x128  = 32768
#define OFF_W3  49152      // 512x256  = 131072
#define OFF_L1  180224     // 1024x512 = 524288
#define OFF_L2  704512     // 512x1024 = 524288  -> end 1228800

// ================= device scratch (no allocations allowed) =================
__device__ int   g_cnt[NN];
__device__ int   g_rowptr[NN + 1];
__device__ int   g_cursor[NN];
__device__ int   g_bsum[NBLK];
__device__ int2  g_edge[NE];                  // (src, wgt bits) packed
__device__ float g_is[NN];
__device__ __half g_Ahi[(size_t)NN * 256];
__device__ __half g_Alo[(size_t)NN * 256];
__device__ __half g_act1[(size_t)NN * 1024];
__device__ __half g_act2[(size_t)NN * 1024];
__device__ __half g_Whi[1 << 21];
__device__ __half g_Wlo[1 << 15];             // only W1 needs a lo plane
__device__ float g_nsum[(size_t)NN * 4];
__device__ float g_gsum[NG * 4];
__device__ int   g_gcnt[NG];

__device__ __forceinline__ uint32_t smem_u32(const void* p) {
    uint32_t a;
    asm("{ .reg .u64 t; cvta.to.shared.u64 t, %1; cvt.u32.u64 %0, t; }" : "=r"(a) : "l"(p));
    return a;
}

// ================= graph preprocessing =================
__global__ void zero_kernel() {
    int i = blockIdx.x * blockDim.x + threadIdx.x;
    if (i < NN) g_cnt[i] = 0;
    if (i < NN * 4) g_nsum[i] = 0.f;
    if (i < NG * 4) g_gsum[i] = 0.f;
    if (i < NG) g_gcnt[i] = 0;
}

__global__ void hist_kernel(const int* __restrict__ dst) {
    int e = blockIdx.x * blockDim.x + threadIdx.x;
    if (e < NE) atomicAdd(&g_cnt[dst[e]], 1);
}

__global__ void invsqrt_kernel() {
    int i = blockIdx.x * blockDim.x + threadIdx.x;
    if (i < NN) g_is[i] = rsqrtf((float)(g_cnt[i] + 1));
}

__global__ void scan1_kernel() {
    int i = blockIdx.x * 256 + threadIdx.x;
    int v = (i < NN) ? g_cnt[i] : 0;
#pragma unroll
    for (int o = 16; o > 0; o >>= 1) v += __shfl_down_sync(0xffffffffu, v, o);
    __shared__ int ws[8];
    if ((threadIdx.x & 31) == 0) ws[threadIdx.x >> 5] = v;
    __syncthreads();
    if (threadIdx.x < 8) {
        int s = ws[threadIdx.x];
#pragma unroll
        for (int o = 4; o > 0; o >>= 1) s += __shfl_down_sync(0xffu, s, o);
        if (threadIdx.x == 0) g_bsum[blockIdx.x] = s;
    }
}

__global__ void scan2_kernel() {
    int tid = threadIdx.x;
    int v = (tid < NBLK) ? g_bsum[tid] : 0;
    __shared__ int sm[512];
    sm[tid] = v;
    __syncthreads();
    for (int o = 1; o < 512; o <<= 1) {
        int a = (tid >= o) ? sm[tid - o] : 0;
        __syncthreads();
        sm[tid] += a;
        __syncthreads();
    }
    if (tid < NBLK) g_bsum[tid] = sm[tid] - v;
    if (tid == NBLK - 1) g_rowptr[NN] = sm[tid];
}

__global__ void scan3_kernel() {
    int i = blockIdx.x * 256 + threadIdx.x;
    int v = (i < NN) ? g_cnt[i] : 0;
    int lane = threadIdx.x & 31, w = threadIdx.x >> 5;
    int x = v;
#pragma unroll
    for (int o = 1; o < 32; o <<= 1) {
        int t = __shfl_up_sync(0xffffffffu, x, o);
        if (lane >= o) x += t;
    }
    __shared__ int ws[8];
    if (lane == 31) ws[w] = x;
    __syncthreads();
    if (threadIdx.x < 8) {
        int s = ws[threadIdx.x];
#pragma unroll
        for (int o = 1; o < 8; o <<= 1) {
            int t = __shfl_up_sync(0xffu, s, o);
            if ((int)threadIdx.x >= o) s += t;
        }
        ws[threadIdx.x] = s;
    }
    __syncthreads();
    int excl = x - v + (w ? ws[w - 1] : 0) + g_bsum[blockIdx.x];
    if (i < NN) {
        g_rowptr[i] = excl;
        g_cursor[i] = excl;
    }
}

__global__ void csr_fill_kernel(const int* __restrict__ src, const int* __restrict__ dst) {
    int e = blockIdx.x * blockDim.x + threadIdx.x;
    if (e >= NE) return;
    int d = dst[e];
    int s = src[e];
    int p = atomicAdd(&g_cursor[d], 1);
    g_edge[p] = make_int2(s, __float_as_int(g_is[s] * g_is[d]));
}

// ================= fp32 x -> fp16 plane =================
__global__ void xconv_kernel(const float* __restrict__ x, __half* __restrict__ o, size_t total) {
    size_t i = blockIdx.x * (size_t)blockDim.x + threadIdx.x;
    if (i < total) o[i] = __float2half_rn(x[i]);
}

// ================= aggregation: fp16 gather, fp32 accum =================
// LO=1: emit hi+lo planes (for 3-term GEMM). LO=0: hi plane only.
template <int H, int LO>
__global__ void agg16_kernel(const __half* __restrict__ h,
                             __half* __restrict__ outHi, __half* __restrict__ outLo) {
    const int node = blockIdx.x * 4 + (threadIdx.x >> 5);
    if (node >= NN) return;
    const int lane = threadIdx.x & 31;
    constexpr int U = H / 128;

    float acc[U][4];
    float self = g_is[node];
    self = self * self;
    const uint2* hrow = (const uint2*)(h + (size_t)node * H);
#pragma unroll
    for (int u = 0; u < U; u++) {
        uint2 t = hrow[lane + 32 * u];
        float2 a = __half22float2(*(const __half2*)&t.x);
        float2 b = __half22float2(*(const __half2*)&t.y);
        acc[u][0] = self * a.x; acc[u][1] = self * a.y;
        acc[u][2] = self * b.x; acc[u][3] = self * b.y;
    }
    const int beg = g_rowptr[node];
    const int end = g_rowptr[node + 1];
    int p = beg;
    for (; p + 2 <= end; p += 2) {
        int2 e0 = g_edge[p], e1 = g_edge[p + 1];
        float w0 = __int_as_float(e0.y), w1 = __int_as_float(e1.y);
        const uint2* s0 = (const uint2*)(h + (size_t)e0.x * H);
        const uint2* s1 = (const uint2*)(h + (size_t)e1.x * H);
#pragma unroll
        for (int u = 0; u < U; u++) {
            uint2 t0 = s0[lane + 32 * u];
            uint2 t1 = s1[lane + 32 * u];
            float2 a0 = __half22float2(*(const __half2*)&t0.x);
            float2 b0 = __half22float2(*(const __half2*)&t0.y);
            float2 a1 = __half22float2(*(const __half2*)&t1.x);
            float2 b1 = __half22float2(*(const __half2*)&t1.y);
            acc[u][0] += w0 * a0.x + w1 * a1.x;
            acc[u][1] += w0 * a0.y + w1 * a1.y;
            acc[u][2] += w0 * b0.x + w1 * b1.x;
            acc[u][3] += w0 * b0.y + w1 * b1.y;
        }
    }
    if (p < end) {
        int2 e0 = g_edge[p];
        float w0 = __int_as_float(e0.y);
        const uint2* s0 = (const uint2*)(h + (size_t)e0.x * H);
#pragma unroll
        for (int u = 0; u < U; u++) {
            uint2 t0 = s0[lane + 32 * u];
            float2 a0 = __half22float2(*(const __half2*)&t0.x);
            float2 b0 = __half22float2(*(const __half2*)&t0.y);
            acc[u][0] += w0 * a0.x; acc[u][1] += w0 * a0.y;
            acc[u][2] += w0 * b0.x; acc[u][3] += w0 * b0.y;
        }
    }
#pragma unroll
    for (int u = 0; u < U; u++) {
        ushort hs[4], ls[4];
#pragma unroll
        for (int q = 0; q < 4; q++) {
            __half hh = __float2half_rn(acc[u][q]);
            hs[q] = __half_as_ushort(hh);
            if (LO) ls[q] = __half_as_ushort(__float2half_rn(acc[u][q] - __half2float(hh)));
        }
        uint2 ph = make_uint2((uint32_t)hs[0] | ((uint32_t)hs[1] << 16),
                              (uint32_t)hs[2] | ((uint32_t)hs[3] << 16));
        ((uint2*)(outHi + (size_t)node * H))[lane + 32 * u] = ph;
        if (LO) {
            uint2 pl = make_uint2((uint32_t)ls[0] | ((uint32_t)ls[1] << 16),
                                  (uint32_t)ls[2] | ((uint32_t)ls[3] << 16));
            ((uint2*)(outLo + (size_t)node * H))[lane + 32 * u] = pl;
        }
    }
}

// ================= fp32 -> fp16 weight conversion (transposed, offset) =======
__global__ void wconv_kernel(const float* __restrict__ W, int K, int N, int off, int both) {
    int idx = blockIdx.x * blockDim.x + threadIdx.x;
    if (idx >= N * K) return;
    int n = idx / K, k = idx - n * K;
    float v = W[(size_t)k * N + n];
    __half hi = __float2half_rn(v);
    g_Whi[off + idx] = hi;
    if (both) g_Wlo[idx] = __float2half_rn(v - __half2float(hi));
}

// ================= tensor-core GEMM (fp16, mma.sync) =========================
#define MMA_F16(ACC, AF, B0, B1)                                                 \
    asm volatile(                                                                \
        "mma.sync.aligned.m16n8k16.row.col.f32.f16.f16.f32 "                     \
        "{%0,%1,%2,%3}, {%4,%5,%6,%7}, {%8,%9}, {%0,%1,%2,%3};"                  \
        : "+f"((ACC)[0]), "+f"((ACC)[1]), "+f"((ACC)[2]), "+f"((ACC)[3])         \
        : "r"((AF)[0]), "r"((AF)[1]), "r"((AF)[2]), "r"((AF)[3]),                \
          "r"(B0), "r"(B1))

// NPROD 3: AhiWhi+AloWhi+AhiWlo. NPROD 1: Ahi*Whi.
// OUTMODE 0: fp16 plane out. OUTMODE 1: fused 512->4 dot + node-sum.
template <int BN, int NPROD, int OUTMODE>
__global__ __launch_bounds__(256) void gemm_mma(
    const __half* __restrict__ Ahi, const __half* __restrict__ Alo,
    const __half* __restrict__ Whi, const __half* __restrict__ Wlo,
    const float* __restrict__ bias, int M, int K, int N, int relu,
    __half* __restrict__ outH,
    const float* __restrict__ lw3, float* __restrict__ nsum) {
    constexpr int NA = BN / 32;
    constexpr int NPA = (NPROD == 3) ? 2 : 1;
    constexpr int STAGE_A = 128 * 64 * NPA;
    constexpr int STAGE_B = BN * 64 * NPA;
    constexpr int STAGE = STAGE_A + STAGE_B;

    extern __shared__ char dynsm[];
    const uint32_t base0 = (smem_u32(dynsm) + 1023u) & ~1023u;

    const int tid = threadIdx.x;
    const int lane = tid & 31, wid = tid >> 5;
    const int wm = wid & 1, wn = wid >> 1;
    const int m0 = blockIdx.y * 128, n0 = blockIdx.x * BN;
    const int nch = K >> 5;

    float acc[4][NA][4];
#pragma unroll
    for (int i = 0; i < 4; i++)
#pragma unroll
        for (int j = 0; j < NA; j++)
#pragma unroll
            for (int q = 0; q < 4; q++) acc[i][j][q] = 0.f;

    auto fill = [&](int ci, int buf) {
        const int kb = ci * 64;
        const uint32_t st = base0 + buf * STAGE;
#pragma unroll
        for (int p = 0; p < NPA; p++) {
            const __half* Ap = p ? Alo : Ahi;
            const uint32_t dA = st + p * 8192;
#pragma unroll
            for (int i = 0; i < 2; i++) {
                int t2 = tid + i * 256;
                int r = t2 >> 2, c = t2 & 3;
                int row = m0 + r;
                int rowc = (row < M) ? row : (M - 1);
                const char* src = (const char*)(Ap + (size_t)rowc * K) + kb + c * 16;
                uint32_t ssize = (row < M) ? 16u : 0u;
                uint32_t dst = dA + (uint32_t)(r * 64 + ((c ^ ((r >> 1) & 3)) * 16));
                asm volatile("cp.async.cg.shared.global [%0], [%1], 16, %2;"
                             :: "r"(dst), "l"(src), "r"(ssize) : "memory");
            }
        }
#pragma unroll
        for (int p = 0; p < NPA; p++) {
            const __half* Wp = p ? Wlo : Whi;
            const uint32_t dB = st + STAGE_A + p * (BN * 64);
#pragma unroll
            for (int i = 0; i < BN / 64; i++) {
                int t2 = tid + i * 256;
                int r = t2 >> 2, c = t2 & 3;
                const char* src = (const char*)(Wp + (size_t)(n0 + r) * K) + kb + c * 16;
                uint32_t dst = dB + (uint32_t)(r * 64 + ((c ^ ((r >> 1) & 3)) * 16));
                asm volatile("cp.async.cg.shared.global [%0], [%1], 16;"
                             :: "r"(dst), "l"(src) : "memory");
            }
        }
        asm volatile("cp.async.commit_group;" ::: "memory");
    };

    auto compute = [&](int buf) {
        const uint32_t st = base0 + buf * STAGE;
        const uint32_t aHiB = st, aLoB = st + 8192;
        const uint32_t bHiB = st + STAGE_A, bLoB = st + STAGE_A + BN * 64;
#pragma unroll
        for (int ks = 0; ks < 2; ks++) {
            uint32_t ah[4][4], al[4][4];
#pragma unroll
            for (int ma = 0; ma < 4; ma++) {
                int r = wm * 64 + ma * 16 + (lane & 15);
                int c = ks * 2 + (lane >> 4);
                uint32_t off = (uint32_t)(r * 64 + ((c ^ ((r >> 1) & 3)) * 16));
                asm volatile("ldmatrix.sync.aligned.m8n8.x4.shared.b16 {%0,%1,%2,%3}, [%4];"
                             : "=r"(ah[ma][0]), "=r"(ah[ma][1]), "=r"(ah[ma][2]), "=r"(ah[ma][3])
                             : "r"(aHiB + off));
                if (NPROD == 3)
                    asm volatile("ldmatrix.sync.aligned.m8n8.x4.shared.b16 {%0,%1,%2,%3}, [%4];"
                                 : "=r"(al[ma][0]), "=r"(al[ma][1]), "=r"(al[ma][2]), "=r"(al[ma][3])
                                 : "r"(aLoB + off));
            }
#pragma unroll
            for (int nb = 0; nb < NA / 2; nb++) {
                int r = wn * (BN / 4) + nb * 16 + (lane & 7) + ((lane >> 4) & 1) * 8;
                int c = ks * 2 + ((lane >> 3) & 1);
                uint32_t off = (uint32_t)(r * 64 + ((c ^ ((r >> 1) & 3)) * 16));
                uint32_t b0, b1, b2, b3;
                asm volatile("ldmatrix.sync.aligned.m8n8.x4.shared.b16 {%0,%1,%2,%3}, [%4];"
                             : "=r"(b0), "=r"(b1), "=r"(b2), "=r"(b3) : "r"(bHiB + off));
#pragma unroll
                for (int ma = 0; ma < 4; ma++) {
                    MMA_F16(acc[ma][nb * 2], ah[ma], b0, b1);
                    MMA_F16(acc[ma][nb * 2 + 1], ah[ma], b2, b3);
                    if (NPROD == 3) {
                        MMA_F16(acc[ma][nb * 2], al[ma], b0, b1);
                        MMA_F16(acc[ma][nb * 2 + 1], al[ma], b2, b3);
                    }
                }
                if (NPROD == 3) {
                    asm volatile("ldmatrix.sync.aligned.m8n8.x4.shared.b16 {%0,%1,%2,%3}, [%4];"
                                 : "=r"(b0), "=r"(b1), "=r"(b2), "=r"(b3) : "r"(bLoB + off));
#pragma unroll
                    for (int ma = 0; ma < 4; ma++) {
                        MMA_F16(acc[ma][nb * 2], ah[ma], b0, b1);
                        MMA_F16(acc[ma][nb * 2 + 1], ah[ma], b2, b3);
                    }
                }
            }
        }
    };

    fill(0, 0);
    fill(1, 1);
    for (int ci = 0; ci < nch; ci++) {
        if (ci + 1 < nch) {
            asm volatile("cp.async.wait_group 1;" ::: "memory");
        } else {
            asm volatile("cp.async.wait_group 0;" ::: "memory");
        }
        __syncthreads();
        if (ci + 2 < nch) fill(ci + 2, (ci + 2) % 3);
        compute(ci % 3);
    }

    // ---- epilogue ----
#pragma unroll
    for (int ma = 0; ma < 4; ma++) {
        int r0 = m0 + wm * 64 + ma * 16 + (lane >> 2);
        float p0[4] = {0.f, 0.f, 0.f, 0.f}, p1[4] = {0.f, 0.f, 0.f, 0.f};
#pragma unroll
        for (int na = 0; na < NA; na++) {
            int c = n0 + wn * (BN / 4) + na * 8 + (lane & 3) * 2;
            float b0v = __ldg(bias + c), b1v = __ldg(bias + c + 1);
            float v00 = acc[ma][na][0] + b0v, v01 = acc[ma][na][1] + b1v;
            float v10 = acc[ma][na][2] + b0v, v11 = acc[ma][na][3] + b1v;
            if (relu) {
                v00 = fmaxf(v00, 0.f); v01 = fmaxf(v01, 0.f);
                v10 = fmaxf(v10, 0.f); v11 = fmaxf(v11, 0.f);
            }
            if (OUTMODE == 0) {
#pragma unroll
                for (int rr = 0; rr < 2; rr++) {
                    int row = r0 + rr * 8;
                    if (row >= M) continue;
                    float va = rr ? v10 : v00, vb = rr ? v11 : v01;
                    uint32_t hp = (uint32_t)__half_as_ushort(__float2half_rn(va)) |
                                  ((uint32_t)__half_as_ushort(__float2half_rn(vb)) << 16);
                    *(uint32_t*)(outH + (size_t)row * N + c) = hp;
                }
            } else {
                float4 w0 = __ldg((const float4*)(lw3 + c * 4));
                float4 w1 = __ldg((const float4*)(lw3 + (c + 1) * 4));
                p0[0] += v00 * w0.x + v01 * w1.x;  p0[1] += v00 * w0.y + v01 * w1.y;
                p0[2] += v00 * w0.z + v01 * w1.z;  p0[3] += v00 * w0.w + v01 * w1.w;
                p1[0] += v10 * w0.x + v11 * w1.x;  p1[1] += v10 * w0.y + v11 * w1.y;
                p1[2] += v10 * w0.z + v11 * w1.z;  p1[3] += v10 * w0.w + v11 * w1.w;
            }
        }
        if (OUTMODE == 1) {
#pragma unroll
            for (int j = 0; j < 4; j++) {
                p0[j] += __shfl_down_sync(0xffffffffu, p0[j], 2);
                p0[j] += __shfl_down_sync(0xffffffffu, p0[j], 1);
                p1[j] += __shfl_down_sync(0xffffffffu, p1[j], 2);
                p1[j] += __shfl_down_sync(0xffffffffu, p1[j], 1);
            }
            if ((lane & 3) == 0) {
                if (r0 < M) {
#pragma unroll
                    for (int j = 0; j < 4; j++) atomicAdd(&nsum[(size_t)r0 * 4 + j], p0[j]);
                }
                if (r0 + 8 < M) {
#pragma unroll
                    for (int j = 0; j < 4; j++) atomicAdd(&nsum[(size_t)(r0 + 8) * 4 + j], p1[j]);
                }
            }
        }
    }
}

// ================= pooling (warp-aggregated) =================
__global__ void pool_kernel(const int* __restrict__ batch) {
    int i = blockIdx.x * 256 + threadIdx.x;
    int lane = threadIdx.x & 31;
    bool valid = i < NN;
    int g = valid ? batch[i] : -1;
    float4 v = valid ? *(const float4*)(g_nsum + (size_t)i * 4)
                     : make_float4(0.f, 0.f, 0.f, 0.f);
    int g0 = __shfl_sync(0xffffffffu, g, 0);
    bool uni = __all_sync(0xffffffffu, valid && g == g0);
    if (uni) {
#pragma unroll
        for (int o = 16; o > 0; o >>= 1) {
            v.x += __shfl_down_sync(0xffffffffu, v.x, o);
            v.y += __shfl_down_sync(0xffffffffu, v.y, o);
            v.z += __shfl_down_sync(0xffffffffu, v.z, o);
            v.w += __shfl_down_sync(0xffffffffu, v.w, o);
        }
        if (lane == 0) {
            atomicAdd(&g_gsum[g0 * 4 + 0], v.x);
            atomicAdd(&g_gsum[g0 * 4 + 1], v.y);
            atomicAdd(&g_gsum[g0 * 4 + 2], v.z);
            atomicAdd(&g_gsum[g0 * 4 + 3], v.w);
            atomicAdd(&g_gcnt[g0], 32);
        }
    } else if (valid) {
        atomicAdd(&g_gsum[g * 4 + 0], v.x);
        atomicAdd(&g_gsum[g * 4 + 1], v.y);
        atomicAdd(&g_gsum[g * 4 + 2], v.z);
        atomicAdd(&g_gsum[g * 4 + 3], v.w);
        atomicAdd(&g_gcnt[g], 1);
    }
}

__global__ void finalize_kernel(float* __restrict__ out, const float* __restrict__ lb3) {
    int i = blockIdx.x * blockDim.x + threadIdx.x;
    if (i < NG * 4) {
        int cnt = g_gcnt[i >> 2];
        out[i] = (cnt > 0) ? (g_gsum[i] / (float)cnt + lb3[i & 3]) : 0.f;
    }
}

// ================= launch =================
extern "C" void kernel_launch(void* const* d_in, const int* in_sizes, int n_in,
                              void* d_out, int out_size) {
    const float* x    = (const float*)d_in[0];
    const int*   ei   = (const int*)d_in[1];
    const int*   bat  = (const int*)d_in[2];
    const float* W1   = (const float*)d_in[3];
    const float* b1   = (const float*)d_in[4];
    const float* W2   = (const float*)d_in[5];
    const float* b2   = (const float*)d_in[6];
    const float* W3   = (const float*)d_in[7];
    const float* b3   = (const float*)d_in[8];
    const float* lw1  = (const float*)d_in[9];
    const float* lb1  = (const float*)d_in[10];
    const float* lw2  = (const float*)d_in[11];
    const float* lb2  = (const float*)d_in[12];
    const float* lw3  = (const float*)d_in[13];
    const float* lb3  = (const float*)d_in[14];
    float* out = (float*)d_out;

    const int* src = ei;
    const int* dst = ei + NE;

    float* nsum;
    cudaGetSymbolAddress((void**)&nsum, g_nsum);
    __half *Ahi, *Alo, *act1, *act2, *Whi, *Wlo;
    cudaGetSymbolAddress((void**)&Ahi, g_Ahi);
    cudaGetSymbolAddress((void**)&Alo, g_Alo);
    cudaGetSymbolAddress((void**)&act1, g_act1);
    cudaGetSymbolAddress((void**)&act2, g_act2);
    cudaGetSymbolAddress((void**)&Whi, g_Whi);
    cudaGetSymbolAddress((void**)&Wlo, g_Wlo);

    constexpr int SM_128_3 = 3 * (2 * 8192 + 128 * 64 * 2) + 1024;  // 99328
    constexpr int SM_256_1 = 3 * (8192 + 256 * 64) + 1024;          // 74752
    cudaFuncSetAttribute(gemm_mma<128, 3, 0>, cudaFuncAttributeMaxDynamicSharedMemorySize, SM_128_3);
    cudaFuncSetAttribute(gemm_mma<256, 1, 0>, cudaFuncAttributeMaxDynamicSharedMemorySize, SM_256_1);
    cudaFuncSetAttribute(gemm_mma<256, 1, 1>, cudaFuncAttributeMaxDynamicSharedMemorySize, SM_256_1);

    // ---- all weight conversions upfront ----
    wconv_kernel<<<(128 * 128 + 255) / 256, 256>>>(W1, 128, 128, OFF_W1, 1);
    wconv_kernel<<<(256 * 128 + 255) / 256, 256>>>(W2, 128, 256, OFF_W2, 0);
    wconv_kernel<<<(512 * 256 + 255) / 256, 256>>>(W3, 256, 512, OFF_W3, 0);
    wconv_kernel<<<(1024 * 512 + 255) / 256, 256>>>(lw1, 512, 1024, OFF_L1, 0);
    wconv_kernel<<<(512 * 1024 + 255) / 256, 256>>>(lw2, 1024, 512, OFF_L2, 0);
    xconv_kernel<<<(int)(((size_t)NN * 128 + 255) / 256), 256>>>(x, act1, (size_t)NN * 128);

    // ---- graph preprocessing ----
    zero_kernel<<<(NN * 4 + 255) / 256, 256>>>();
    hist_kernel<<<(NE + 255) / 256, 256>>>(dst);
    invsqrt_kernel<<<(NN + 255) / 256, 256>>>();
    scan1_kernel<<<NBLK, 256>>>();
    scan2_kernel<<<1, 512>>>();
    scan3_kernel<<<NBLK, 256>>>();
    csr_fill_kernel<<<(NE + 255) / 256, 256>>>(src, dst);

    const int aggBlocks = (NN + 3) / 4;
    const int tilesM = (NN + 127) / 128;   // 782

    // ---- layer 1: agg (hi+lo), 3-term mma (K=128, N=128) ----
    agg16_kernel<128, 1><<<aggBlocks, 128>>>(act1, Ahi, Alo);
    gemm_mma<128, 3, 0><<<dim3(1, tilesM), 256, SM_128_3>>>(
        Ahi, Alo, Whi + OFF_W1, Wlo, b1, NN, 128, 128, 1, act1, nullptr, nullptr);

    // ---- layer 2: agg (hi only), 1-term (K=128, N=256) ----
    agg16_kernel<128, 0><<<aggBlocks, 128>>>(act1, Ahi, nullptr);
    gemm_mma<256, 1, 0><<<dim3(1, tilesM), 256, SM_256_1>>>(
        Ahi, nullptr, Whi + OFF_W2, nullptr, b2, NN, 128, 256, 1, act1, nullptr, nullptr);

    // ---- layer 3: agg (hi only), 1-term (K=256, N=512) ----
    agg16_kernel<256, 0><<<aggBlocks, 128>>>(act1, Ahi, nullptr);
    gemm_mma<256, 1, 0><<<dim3(2, tilesM), 256, SM_256_1>>>(
        Ahi, nullptr, Whi + OFF_W3, nullptr, b3, NN, 256, 512, 0, act1, nullptr, nullptr);

    // ---- MLP1: pure fp16 (K=512, N=1024) ----
    gemm_mma<256, 1, 0><<<dim3(4, tilesM), 256, SM_256_1>>>(
        act1, nullptr, Whi + OFF_L1, nullptr, lb1, NN, 512, 1024, 1, act2, nullptr, nullptr);

    // ---- MLP2: pure fp16 (K=1024, N=512), fused 512->4 + node-sum ----
    gemm_mma<256, 1, 1><<<dim3(2, tilesM), 256, SM_256_1>>>(
        act2, nullptr, Whi + OFF_L2, nullptr, lb2, NN, 1024, 512, 1, nullptr, lw3, nsum);

    // ---- pooling ----
    pool_kernel<<<NBLK, 256>>>(bat);
    finalize_kernel<<<(NG * 4 + 255) / 256, 256>>>(out, lb3);
}

// round 12
// speedup vs baseline: 5.3465x; 1.0251x over previous
#include <cuda_runtime.h>
#include <cuda_fp16.h>
#include <cstdint>

#define NN 100000
#define NE 3200000
#define NG 256
#define NBLK 391   // ceil(NN/256)

// ---- weight plane offsets (elements) ----
#define OFF_W1  0          // 128x128  = 16384
#define OFF_W2  16384      // 256x128  = 32768
#define OFF_W3  49152      // 512x256  = 131072
#define OFF_L1  180224     // 1024x512 = 524288
#define OFF_L2  704512     // 512x1024 = 524288  -> end 1228800

// ================= device scratch (no allocations allowed) =================
__device__ int   g_cnt[NN];
__device__ int   g_rowptr[NN + 1];
__device__ int   g_cursor[NN];
__device__ int   g_bsum[NBLK];
__device__ int2  g_edge[NE];                  // (src, wgt bits) packed
__device__ float g_is[NN];
__device__ __half g_Ahi[(size_t)NN * 256];
__device__ __half g_act1[(size_t)NN * 1024];
__device__ __half g_act2[(size_t)NN * 1024];
__device__ __half g_Whi[1 << 21];
__device__ float g_nsum[(size_t)NN * 4];
__device__ float g_gsum[NG * 4];
__device__ int   g_gcnt[NG];

__device__ __forceinline__ uint32_t smem_u32(const void* p) {
    uint32_t a;
    asm("{ .reg .u64 t; cvta.to.shared.u64 t, %1; cvt.u32.u64 %0, t; }" : "=r"(a) : "l"(p));
    return a;
}

// ================= graph preprocessing =================
__global__ void zero_kernel() {
    int i = blockIdx.x * blockDim.x + threadIdx.x;
    if (i < NN) g_cnt[i] = 0;
    if (i < NN * 4) g_nsum[i] = 0.f;
    if (i < NG * 4) g_gsum[i] = 0.f;
    if (i < NG) g_gcnt[i] = 0;
}

__global__ void hist_kernel(const int* __restrict__ dst) {
    int e = blockIdx.x * blockDim.x + threadIdx.x;
    if (e < NE) atomicAdd(&g_cnt[dst[e]], 1);
}

__global__ void invsqrt_kernel() {
    int i = blockIdx.x * blockDim.x + threadIdx.x;
    if (i < NN) g_is[i] = rsqrtf((float)(g_cnt[i] + 1));
}

__global__ void scan1_kernel() {
    int i = blockIdx.x * 256 + threadIdx.x;
    int v = (i < NN) ? g_cnt[i] : 0;
#pragma unroll
    for (int o = 16; o > 0; o >>= 1) v += __shfl_down_sync(0xffffffffu, v, o);
    __shared__ int ws[8];
    if ((threadIdx.x & 31) == 0) ws[threadIdx.x >> 5] = v;
    __syncthreads();
    if (threadIdx.x < 8) {
        int s = ws[threadIdx.x];
#pragma unroll
        for (int o = 4; o > 0; o >>= 1) s += __shfl_down_sync(0xffu, s, o);
        if (threadIdx.x == 0) g_bsum[blockIdx.x] = s;
    }
}

__global__ void scan2_kernel() {
    int tid = threadIdx.x;
    int v = (tid < NBLK) ? g_bsum[tid] : 0;
    __shared__ int sm[512];
    sm[tid] = v;
    __syncthreads();
    for (int o = 1; o < 512; o <<= 1) {
        int a = (tid >= o) ? sm[tid - o] : 0;
        __syncthreads();
        sm[tid] += a;
        __syncthreads();
    }
    if (tid < NBLK) g_bsum[tid] = sm[tid] - v;
    if (tid == NBLK - 1) g_rowptr[NN] = sm[tid];
}

__global__ void scan3_kernel() {
    int i = blockIdx.x * 256 + threadIdx.x;
    int v = (i < NN) ? g_cnt[i] : 0;
    int lane = threadIdx.x & 31, w = threadIdx.x >> 5;
    int x = v;
#pragma unroll
    for (int o = 1; o < 32; o <<= 1) {
        int t = __shfl_up_sync(0xffffffffu, x, o);
        if (lane >= o) x += t;
    }
    __shared__ int ws[8];
    if (lane == 31) ws[w] = x;
    __syncthreads();
    if (threadIdx.x < 8) {
        int s = ws[threadIdx.x];
#pragma unroll
        for (int o = 1; o < 8; o <<= 1) {
            int t = __shfl_up_sync(0xffu, s, o);
            if ((int)threadIdx.x >= o) s += t;
        }
        ws[threadIdx.x] = s;
    }
    __syncthreads();
    int excl = x - v + (w ? ws[w - 1] : 0) + g_bsum[blockIdx.x];
    if (i < NN) {
        g_rowptr[i] = excl;
        g_cursor[i] = excl;
    }
}

__global__ void csr_fill_kernel(const int* __restrict__ src, const int* __restrict__ dst) {
    int e = blockIdx.x * blockDim.x + threadIdx.x;
    if (e >= NE) return;
    int d = dst[e];
    int s = src[e];
    int p = atomicAdd(&g_cursor[d], 1);
    g_edge[p] = make_int2(s, __float_as_int(g_is[s] * g_is[d]));
}

// ================= fp32 x -> fp16 plane =================
__global__ void xconv_kernel(const float* __restrict__ x, __half* __restrict__ o, size_t total) {
    size_t i = blockIdx.x * (size_t)blockDim.x + threadIdx.x;
    if (i < total) o[i] = __float2half_rn(x[i]);
}

// ================= aggregation: fp16 gather, fp32 accum, fp16 out ============
template <int H>
__global__ void agg16_kernel(const __half* __restrict__ h, __half* __restrict__ outHi) {
    const int node = blockIdx.x * 4 + (threadIdx.x >> 5);
    if (node >= NN) return;
    const int lane = threadIdx.x & 31;
    constexpr int U = H / 128;

    float acc[U][4];
    float self = g_is[node];
    self = self * self;
    const uint2* hrow = (const uint2*)(h + (size_t)node * H);
#pragma unroll
    for (int u = 0; u < U; u++) {
        uint2 t = hrow[lane + 32 * u];
        float2 a = __half22float2(*(const __half2*)&t.x);
        float2 b = __half22float2(*(const __half2*)&t.y);
        acc[u][0] = self * a.x; acc[u][1] = self * a.y;
        acc[u][2] = self * b.x; acc[u][3] = self * b.y;
    }
    const int beg = g_rowptr[node];
    const int end = g_rowptr[node + 1];
    int p = beg;
    for (; p + 2 <= end; p += 2) {
        int2 e0 = g_edge[p], e1 = g_edge[p + 1];
        float w0 = __int_as_float(e0.y), w1 = __int_as_float(e1.y);
        const uint2* s0 = (const uint2*)(h + (size_t)e0.x * H);
        const uint2* s1 = (const uint2*)(h + (size_t)e1.x * H);
#pragma unroll
        for (int u = 0; u < U; u++) {
            uint2 t0 = s0[lane + 32 * u];
            uint2 t1 = s1[lane + 32 * u];
            float2 a0 = __half22float2(*(const __half2*)&t0.x);
            float2 b0 = __half22float2(*(const __half2*)&t0.y);
            float2 a1 = __half22float2(*(const __half2*)&t1.x);
            float2 b1 = __half22float2(*(const __half2*)&t1.y);
            acc[u][0] += w0 * a0.x + w1 * a1.x;
            acc[u][1] += w0 * a0.y + w1 * a1.y;
            acc[u][2] += w0 * b0.x + w1 * b1.x;
            acc[u][3] += w0 * b0.y + w1 * b1.y;
        }
    }
    if (p < end) {
        int2 e0 = g_edge[p];
        float w0 = __int_as_float(e0.y);
        const uint2* s0 = (const uint2*)(h + (size_t)e0.x * H);
#pragma unroll
        for (int u = 0; u < U; u++) {
            uint2 t0 = s0[lane + 32 * u];
            float2 a0 = __half22float2(*(const __half2*)&t0.x);
            float2 b0 = __half22float2(*(const __half2*)&t0.y);
            acc[u][0] += w0 * a0.x; acc[u][1] += w0 * a0.y;
            acc[u][2] += w0 * b0.x; acc[u][3] += w0 * b0.y;
        }
    }
#pragma unroll
    for (int u = 0; u < U; u++) {
        ushort hs[4];
#pragma unroll
        for (int q = 0; q < 4; q++)
            hs[q] = __half_as_ushort(__float2half_rn(acc[u][q]));
        uint2 ph = make_uint2((uint32_t)hs[0] | ((uint32_t)hs[1] << 16),
                              (uint32_t)hs[2] | ((uint32_t)hs[3] << 16));
        ((uint2*)(outHi + (size_t)node * H))[lane + 32 * u] = ph;
    }
}

// ================= fp32 -> fp16 weight conversion (transposed, offset) =======
__global__ void wconv_kernel(const float* __restrict__ W, int K, int N, int off) {
    int idx = blockIdx.x * blockDim.x + threadIdx.x;
    if (idx >= N * K) return;
    int n = idx / K, k = idx - n * K;
    g_Whi[off + idx] = __float2half_rn(W[(size_t)k * N + n]);
}

// ================= tensor-core GEMM (pure fp16, mma.sync) ====================
#define MMA_F16(ACC, AF, B0, B1)                                                 \
    asm volatile(                                                                \
        "mma.sync.aligned.m16n8k16.row.col.f32.f16.f16.f32 "                     \
        "{%0,%1,%2,%3}, {%4,%5,%6,%7}, {%8,%9}, {%0,%1,%2,%3};"                  \
        : "+f"((ACC)[0]), "+f"((ACC)[1]), "+f"((ACC)[2]), "+f"((ACC)[3])         \
        : "r"((AF)[0]), "r"((AF)[1]), "r"((AF)[2]), "r"((AF)[3]),                \
          "r"(B0), "r"(B1))

// OUTMODE 0: fp16 out. OUTMODE 1: fused 512->4 dot + node-sum.
template <int BN, int OUTMODE>
__global__ __launch_bounds__(256) void gemm_mma(
    const __half* __restrict__ A, const __half* __restrict__ W,
    const float* __restrict__ bias, int M, int K, int N, int relu,
    __half* __restrict__ outH,
    const float* __restrict__ lw3, float* __restrict__ nsum) {
    constexpr int NA = BN / 32;
    constexpr int STAGE_A = 128 * 64;
    constexpr int STAGE_B = BN * 64;
    constexpr int STAGE = STAGE_A + STAGE_B;

    extern __shared__ char dynsm[];
    const uint32_t base0 = (smem_u32(dynsm) + 1023u) & ~1023u;

    const int tid = threadIdx.x;
    const int lane = tid & 31, wid = tid >> 5;
    const int wm = wid & 1, wn = wid >> 1;
    const int m0 = blockIdx.y * 128, n0 = blockIdx.x * BN;
    const int nch = K >> 5;

    float acc[4][NA][4];
#pragma unroll
    for (int i = 0; i < 4; i++)
#pragma unroll
        for (int j = 0; j < NA; j++)
#pragma unroll
            for (int q = 0; q < 4; q++) acc[i][j][q] = 0.f;

    auto fill = [&](int ci, int buf) {
        const int kb = ci * 64;
        const uint32_t st = base0 + buf * STAGE;
#pragma unroll
        for (int i = 0; i < 2; i++) {
            int t2 = tid + i * 256;
            int r = t2 >> 2, c = t2 & 3;
            int row = m0 + r;
            int rowc = (row < M) ? row : (M - 1);
            const char* src = (const char*)(A + (size_t)rowc * K) + kb + c * 16;
            uint32_t ssize = (row < M) ? 16u : 0u;
            uint32_t dst = st + (uint32_t)(r * 64 + ((c ^ ((r >> 1) & 3)) * 16));
            asm volatile("cp.async.cg.shared.global [%0], [%1], 16, %2;"
                         :: "r"(dst), "l"(src), "r"(ssize) : "memory");
        }
#pragma unroll
        for (int i = 0; i < BN / 64; i++) {
            int t2 = tid + i * 256;
            int r = t2 >> 2, c = t2 & 3;
            const char* src = (const char*)(W + (size_t)(n0 + r) * K) + kb + c * 16;
            uint32_t dst = st + STAGE_A + (uint32_t)(r * 64 + ((c ^ ((r >> 1) & 3)) * 16));
            asm volatile("cp.async.cg.shared.global [%0], [%1], 16;"
                         :: "r"(dst), "l"(src) : "memory");
        }
        asm volatile("cp.async.commit_group;" ::: "memory");
    };

    auto compute = [&](int buf) {
        const uint32_t st = base0 + buf * STAGE;
        const uint32_t aB = st, bB = st + STAGE_A;
#pragma unroll
        for (int ks = 0; ks < 2; ks++) {
            uint32_t ah[4][4];
#pragma unroll
            for (int ma = 0; ma < 4; ma++) {
                int r = wm * 64 + ma * 16 + (lane & 15);
                int c = ks * 2 + (lane >> 4);
                uint32_t off = (uint32_t)(r * 64 + ((c ^ ((r >> 1) & 3)) * 16));
                asm volatile("ldmatrix.sync.aligned.m8n8.x4.shared.b16 {%0,%1,%2,%3}, [%4];"
                             : "=r"(ah[ma][0]), "=r"(ah[ma][1]), "=r"(ah[ma][2]), "=r"(ah[ma][3])
                             : "r"(aB + off));
            }
#pragma unroll
            for (int nb = 0; nb < NA / 2; nb++) {
                int r = wn * (BN / 4) + nb * 16 + (lane & 7) + ((lane >> 4) & 1) * 8;
                int c = ks * 2 + ((lane >> 3) & 1);
                uint32_t off = (uint32_t)(r * 64 + ((c ^ ((r >> 1) & 3)) * 16));
                uint32_t b0, b1, b2, b3;
                asm volatile("ldmatrix.sync.aligned.m8n8.x4.shared.b16 {%0,%1,%2,%3}, [%4];"
                             : "=r"(b0), "=r"(b1), "=r"(b2), "=r"(b3) : "r"(bB + off));
#pragma unroll
                for (int ma = 0; ma < 4; ma++) {
                    MMA_F16(acc[ma][nb * 2], ah[ma], b0, b1);
                    MMA_F16(acc[ma][nb * 2 + 1], ah[ma], b2, b3);
                }
            }
        }
    };

    fill(0, 0);
    fill(1, 1);
    for (int ci = 0; ci < nch; ci++) {
        if (ci + 1 < nch) {
            asm volatile("cp.async.wait_group 1;" ::: "memory");
        } else {
            asm volatile("cp.async.wait_group 0;" ::: "memory");
        }
        __syncthreads();
        if (ci + 2 < nch) fill(ci + 2, (ci + 2) % 3);
        compute(ci % 3);
    }

    // ---- epilogue ----
#pragma unroll
    for (int ma = 0; ma < 4; ma++) {
        int r0 = m0 + wm * 64 + ma * 16 + (lane >> 2);
        float p0[4] = {0.f, 0.f, 0.f, 0.f}, p1[4] = {0.f, 0.f, 0.f, 0.f};
#pragma unroll
        for (int na = 0; na < NA; na++) {
            int c = n0 + wn * (BN / 4) + na * 8 + (lane & 3) * 2;
            float b0v = __ldg(bias + c), b1v = __ldg(bias + c + 1);
            float v00 = acc[ma][na][0] + b0v, v01 = acc[ma][na][1] + b1v;
            float v10 = acc[ma][na][2] + b0v, v11 = acc[ma][na][3] + b1v;
            if (relu) {
                v00 = fmaxf(v00, 0.f); v01 = fmaxf(v01, 0.f);
                v10 = fmaxf(v10, 0.f); v11 = fmaxf(v11, 0.f);
            }
            if (OUTMODE == 0) {
#pragma unroll
                for (int rr = 0; rr < 2; rr++) {
                    int row = r0 + rr * 8;
                    if (row >= M) continue;
                    float va = rr ? v10 : v00, vb = rr ? v11 : v01;
                    uint32_t hp = (uint32_t)__half_as_ushort(__float2half_rn(va)) |
                                  ((uint32_t)__half_as_ushort(__float2half_rn(vb)) << 16);
                    *(uint32_t*)(outH + (size_t)row * N + c) = hp;
                }
            } else {
                float4 w0 = __ldg((const float4*)(lw3 + c * 4));
                float4 w1 = __ldg((const float4*)(lw3 + (c + 1) * 4));
                p0[0] += v00 * w0.x + v01 * w1.x;  p0[1] += v00 * w0.y + v01 * w1.y;
                p0[2] += v00 * w0.z + v01 * w1.z;  p0[3] += v00 * w0.w + v01 * w1.w;
                p1[0] += v10 * w0.x + v11 * w1.x;  p1[1] += v10 * w0.y + v11 * w1.y;
                p1[2] += v10 * w0.z + v11 * w1.z;  p1[3] += v10 * w0.w + v11 * w1.w;
            }
        }
        if (OUTMODE == 1) {
#pragma unroll
            for (int j = 0; j < 4; j++) {
                p0[j] += __shfl_down_sync(0xffffffffu, p0[j], 2);
                p0[j] += __shfl_down_sync(0xffffffffu, p0[j], 1);
                p1[j] += __shfl_down_sync(0xffffffffu, p1[j], 2);
                p1[j] += __shfl_down_sync(0xffffffffu, p1[j], 1);
            }
            if ((lane & 3) == 0) {
                if (r0 < M) {
#pragma unroll
                    for (int j = 0; j < 4; j++) atomicAdd(&nsum[(size_t)r0 * 4 + j], p0[j]);
                }
                if (r0 + 8 < M) {
#pragma unroll
                    for (int j = 0; j < 4; j++) atomicAdd(&nsum[(size_t)(r0 + 8) * 4 + j], p1[j]);
                }
            }
        }
    }
}

// ================= pooling (warp-aggregated) =================
__global__ void pool_kernel(const int* __restrict__ batch) {
    int i = blockIdx.x * 256 + threadIdx.x;
    int lane = threadIdx.x & 31;
    bool valid = i < NN;
    int g = valid ? batch[i] : -1;
    float4 v = valid ? *(const float4*)(g_nsum + (size_t)i * 4)
                     : make_float4(0.f, 0.f, 0.f, 0.f);
    int g0 = __shfl_sync(0xffffffffu, g, 0);
    bool uni = __all_sync(0xffffffffu, valid && g == g0);
    if (uni) {
#pragma unroll
        for (int o = 16; o > 0; o >>= 1) {
            v.x += __shfl_down_sync(0xffffffffu, v.x, o);
            v.y += __shfl_down_sync(0xffffffffu, v.y, o);
            v.z += __shfl_down_sync(0xffffffffu, v.z, o);
            v.w += __shfl_down_sync(0xffffffffu, v.w, o);
        }
        if (lane == 0) {
            atomicAdd(&g_gsum[g0 * 4 + 0], v.x);
            atomicAdd(&g_gsum[g0 * 4 + 1], v.y);
            atomicAdd(&g_gsum[g0 * 4 + 2], v.z);
            atomicAdd(&g_gsum[g0 * 4 + 3], v.w);
            atomicAdd(&g_gcnt[g0], 32);
        }
    } else if (valid) {
        atomicAdd(&g_gsum[g * 4 + 0], v.x);
        atomicAdd(&g_gsum[g * 4 + 1], v.y);
        atomicAdd(&g_gsum[g * 4 + 2], v.z);
        atomicAdd(&g_gsum[g * 4 + 3], v.w);
        atomicAdd(&g_gcnt[g], 1);
    }
}

__global__ void finalize_kernel(float* __restrict__ out, const float* __restrict__ lb3) {
    int i = blockIdx.x * blockDim.x + threadIdx.x;
    if (i < NG * 4) {
        int cnt = g_gcnt[i >> 2];
        out[i] = (cnt > 0) ? (g_gsum[i] / (float)cnt + lb3[i & 3]) : 0.f;
    }
}

// ================= launch =================
extern "C" void kernel_launch(void* const* d_in, const int* in_sizes, int n_in,
                              void* d_out, int out_size) {
    const float* x    = (const float*)d_in[0];
    const int*   ei   = (const int*)d_in[1];
    const int*   bat  = (const int*)d_in[2];
    const float* W1   = (const float*)d_in[3];
    const float* b1   = (const float*)d_in[4];
    const float* W2   = (const float*)d_in[5];
    const float* b2   = (const float*)d_in[6];
    const float* W3   = (const float*)d_in[7];
    const float* b3   = (const float*)d_in[8];
    const float* lw1  = (const float*)d_in[9];
    const float* lb1  = (const float*)d_in[10];
    const float* lw2  = (const float*)d_in[11];
    const float* lb2  = (const float*)d_in[12];
    const float* lw3  = (const float*)d_in[13];
    const float* lb3  = (const float*)d_in[14];
    float* out = (float*)d_out;

    const int* src = ei;
    const int* dst = ei + NE;

    float* nsum;
    cudaGetSymbolAddress((void**)&nsum, g_nsum);
    __half *Ahi, *act1, *act2, *Whi;
    cudaGetSymbolAddress((void**)&Ahi, g_Ahi);
    cudaGetSymbolAddress((void**)&act1, g_act1);
    cudaGetSymbolAddress((void**)&act2, g_act2);
    cudaGetSymbolAddress((void**)&Whi, g_Whi);

    constexpr int SM_128 = 3 * (8192 + 128 * 64) + 1024;   // 50176
    constexpr int SM_256 = 3 * (8192 + 256 * 64) + 1024;   // 74752
    cudaFuncSetAttribute(gemm_mma<128, 0>, cudaFuncAttributeMaxDynamicSharedMemorySize, SM_128);
    cudaFuncSetAttribute(gemm_mma<256, 0>, cudaFuncAttributeMaxDynamicSharedMemorySize, SM_256);
    cudaFuncSetAttribute(gemm_mma<256, 1>, cudaFuncAttributeMaxDynamicSharedMemorySize, SM_256);

    // ---- side stream for conversions (fork-join inside graph capture) ----
    static cudaStream_t s2 = nullptr;
    static cudaEvent_t evFork = nullptr, evJoin = nullptr;
    if (s2 == nullptr) {
        cudaStreamCreateWithFlags(&s2, cudaStreamNonBlocking);
        cudaEventCreateWithFlags(&evFork, cudaEventDisableTiming);
        cudaEventCreateWithFlags(&evJoin, cudaEventDisableTiming);
    }

    // fork: conversions run on s2 concurrently with graph preprocessing
    cudaEventRecord(evFork, 0);
    cudaStreamWaitEvent(s2, evFork, 0);

    wconv_kernel<<<(128 * 128 + 255) / 256, 256, 0, s2>>>(W1, 128, 128, OFF_W1);
    wconv_kernel<<<(256 * 128 + 255) / 256, 256, 0, s2>>>(W2, 128, 256, OFF_W2);
    wconv_kernel<<<(512 * 256 + 255) / 256, 256, 0, s2>>>(W3, 256, 512, OFF_W3);
    wconv_kernel<<<(1024 * 512 + 255) / 256, 256, 0, s2>>>(lw1, 512, 1024, OFF_L1);
    wconv_kernel<<<(512 * 1024 + 255) / 256, 256, 0, s2>>>(lw2, 1024, 512, OFF_L2);
    xconv_kernel<<<(int)(((size_t)NN * 128 + 255) / 256), 256, 0, s2>>>(x, act1, (size_t)NN * 128);
    cudaEventRecord(evJoin, s2);

    // ---- graph preprocessing (main stream, concurrent with s2) ----
    zero_kernel<<<(NN * 4 + 255) / 256, 256>>>();
    hist_kernel<<<(NE + 255) / 256, 256>>>(dst);
    invsqrt_kernel<<<(NN + 255) / 256, 256>>>();
    scan1_kernel<<<NBLK, 256>>>();
    scan2_kernel<<<1, 512>>>();
    scan3_kernel<<<NBLK, 256>>>();
    csr_fill_kernel<<<(NE + 255) / 256, 256>>>(src, dst);

    // join: agg1 needs act1 (s2) + CSR (main)
    cudaStreamWaitEvent(0, evJoin, 0);

    const int aggBlocks = (NN + 3) / 4;
    const int tilesM = (NN + 127) / 128;   // 782

    // ---- layer 1 (K=128, N=128) ----
    agg16_kernel<128><<<aggBlocks, 128>>>(act1, Ahi);
    gemm_mma<128, 0><<<dim3(1, tilesM), 256, SM_128>>>(
        Ahi, Whi + OFF_W1, b1, NN, 128, 128, 1, act1, nullptr, nullptr);

    // ---- layer 2 (K=128, N=256) ----
    agg16_kernel<128><<<aggBlocks, 128>>>(act1, Ahi);
    gemm_mma<256, 0><<<dim3(1, tilesM), 256, SM_256>>>(
        Ahi, Whi + OFF_W2, b2, NN, 128, 256, 1, act1, nullptr, nullptr);

    // ---- layer 3 (K=256, N=512) ----
    agg16_kernel<256><<<aggBlocks, 128>>>(act1, Ahi);
    gemm_mma<256, 0><<<dim3(2, tilesM), 256, SM_256>>>(
        Ahi, Whi + OFF_W3, b3, NN, 256, 512, 0, act1, nullptr, nullptr);

    // ---- MLP1 (K=512, N=1024) ----
    gemm_mma<256, 0><<<dim3(4, tilesM), 256, SM_256>>>(
        act1, Whi + OFF_L1, lb1, NN, 512, 1024, 1, act2, nullptr, nullptr);

    // ---- MLP2 (K=1024, N=512), fused 512->4 + node-sum ----
    gemm_mma<256, 1><<<dim3(2, tilesM), 256, SM_256>>>(
        act2, Whi + OFF_L2, lb2, NN, 1024, 512, 1, nullptr, lw3, nsum);

    // ---- pooling ----
    pool_kernel<<<NBLK, 256>>>(bat);
    finalize_kernel<<<(NG * 4 + 255) / 256, 256>>>(out, lb3);
}